// round 11
// baseline (speedup 1.0000x reference)
#include <cuda_runtime.h>
#include <cuda_bf16.h>
#include <math.h>
#include <stdint.h>

#define B_ 8
#define NE_ 1024
#define NO_ 8
#define D_ 1024
#define E_ 8
#define H_ 2048
#define O_ 1024
#define NH_ 8
#define HD_ 128
#define FH_ 4096
#define T_ 8192
#define TM 128
#define TN 128
#define MAXTILES 136
#define SLOTMAX (MAXTILES * TM)

typedef __nv_bfloat16 bf16;

// ---------- device scratch ----------
__device__ float g_xagg[(size_t)T_ * D_];
__device__ float g_ent[(size_t)T_ * O_];
__device__ int   g_topi[T_ * 2];
__device__ float g_gate[T_ * 2];
__device__ int   g_cnt[E_], g_off[E_ + 1], g_fill[E_];
__device__ int   g_tile_e[MAXTILES];
__device__ int   g_slot_tok[SLOTMAX];
__device__ int   g_tok_slot[T_ * 2];
__device__ float g_hbuf[(size_t)SLOTMAX * H_];
__device__ float g_q[(size_t)T_ * O_];
__device__ float g_v[(size_t)T_ * O_];
__device__ float g_scores[(size_t)B_ * NH_ * NE_ * NE_];   // also MoE slot output buffer
__device__ float g_ctx[(size_t)T_ * O_], g_rel[(size_t)T_ * O_];
// pre-split TRANSPOSED weights: Wt[N][K] hi/lo (K-major for non-trans ldmatrix)
__device__ bf16 g_eW1h[(size_t)E_ * D_ * H_], g_eW1l[(size_t)E_ * D_ * H_];
__device__ bf16 g_eW2h[(size_t)E_ * H_ * O_], g_eW2l[(size_t)E_ * H_ * O_];
__device__ bf16 g_Wqh[(size_t)O_ * O_], g_Wql[(size_t)O_ * O_];
__device__ bf16 g_Wkh[(size_t)O_ * O_], g_Wkl[(size_t)O_ * O_];
__device__ bf16 g_Wvh[(size_t)O_ * O_], g_Wvl[(size_t)O_ * O_];
__device__ bf16 g_Woh[(size_t)O_ * O_], g_Wol[(size_t)O_ * O_];
__device__ bf16 g_fW1h[(size_t)O_ * FH_], g_fW1l[(size_t)O_ * FH_];
__device__ bf16 g_fW2h[(size_t)FH_ * O_], g_fW2l[(size_t)FH_ * O_];
// K projection emitted hi/lo by GEMM epilogue (already K-major rows)
__device__ bf16 g_kh[(size_t)T_ * O_], g_kl[(size_t)T_ * O_];
// V transposed+split for ctx: [bh][d][m]
__device__ bf16 g_vth[(size_t)B_ * NH_ * HD_ * NE_], g_vtl[(size_t)B_ * NH_ * HD_ * NE_];

// ---------- helpers ----------
#define SWZ(o) ((o) ^ (((o) >> 3) & 0x70))

__device__ __forceinline__ uint32_t s2u(const void* p) {
    uint32_t a;
    asm("{ .reg .u64 t; cvta.to.shared.u64 t, %1; cvt.u32.u64 %0, t; }" : "=r"(a) : "l"(p));
    return a;
}
__device__ __forceinline__ void split2(float v, bf16& h, bf16& l) {
    h = __float2bfloat16(v);
    l = __float2bfloat16(v - __bfloat162float(h));
}
__device__ __forceinline__ void ldsm4(uint32_t* r, uint32_t addr) {
    asm volatile("ldmatrix.sync.aligned.m8n8.x4.shared.b16 {%0,%1,%2,%3}, [%4];"
                 : "=r"(r[0]), "=r"(r[1]), "=r"(r[2]), "=r"(r[3]) : "r"(addr));
}
__device__ __forceinline__ void mma16816(float* c, const uint32_t* a, const uint32_t* b) {
    asm volatile("mma.sync.aligned.m16n8k16.row.col.f32.bf16.bf16.f32 "
                 "{%0,%1,%2,%3}, {%4,%5,%6,%7}, {%8,%9}, {%0,%1,%2,%3};"
                 : "+f"(c[0]), "+f"(c[1]), "+f"(c[2]), "+f"(c[3])
                 : "r"(a[0]), "r"(a[1]), "r"(a[2]), "r"(a[3]), "r"(b[0]), "r"(b[1]));
}
__device__ __forceinline__ void pack_split(float4 v, uint2& hi, uint2& lo) {
    bf16 h0, l0, h1, l1, h2, l2, h3, l3;
    split2(v.x, h0, l0); split2(v.y, h1, l1);
    split2(v.z, h2, l2); split2(v.w, h3, l3);
    __nv_bfloat162 hA = __halves2bfloat162(h0, h1), hB = __halves2bfloat162(h2, h3);
    __nv_bfloat162 lA = __halves2bfloat162(l0, l1), lB = __halves2bfloat162(l2, l3);
    hi = make_uint2(*(uint32_t*)&hA, *(uint32_t*)&hB);
    lo = make_uint2(*(uint32_t*)&lA, *(uint32_t*)&lB);
}

struct GArgs {
    const float* A; long lda, aSB, aSH;
    const bf16 *Bh, *Bl; long ldb, bSB, bSH, bExp;   // B[N][K] K-major, row stride ldb
    float* C; long ldc, cSB, cSH;
    bf16 *Ch, *Cl;                       // optional bf16 split output
    const float* bias; long biasExp;
    const int* arowIdx; const int* tileE;
    int Kdim, relu;
};

#define TC_SMEM 133120   // 2048 ctrl + 2 * 65536 stages

// ---------- bf16-split tensor-core GEMM (mma.sync, non-trans ldmatrix only) ----------
// CTA 128x128, KC=64, 8 warps (2x4), double-buffered.
// compute() does 3 FULL sweeps (hh, hl, lh) so each acc has dependency distance 16.
__global__ void __launch_bounds__(256, 1) tc_gemm(GArgs g)
{
    int e = 0;
    if (g.tileE) { e = g.tileE[blockIdx.y]; if (e < 0) return; }
    extern __shared__ char smem[];
    char* tiles = (char*)((((uintptr_t)smem) + 1024 + 1023) & ~(uintptr_t)1023);
    const int tid = threadIdx.x, wid = tid >> 5, lid = tid & 31;
    int* srow = (int*)smem;
    const long m0 = (long)blockIdx.y * TM, n0 = (long)blockIdx.x * TN;
    const int z = blockIdx.z, zb = z >> 3, zh = z & 7;

    if (g.arowIdx && tid < TM) srow[tid] = g.arowIdx[m0 + tid];
    __syncthreads();

    const float* Abase = g.A + (size_t)zb * g.aSB + (size_t)zh * g.aSH;
    const bf16* Bhb = g.Bh + (size_t)zb * g.bSB + (size_t)zh * g.bSH + (size_t)e * g.bExp;
    const bf16* Blb = g.Bl + (size_t)zb * g.bSB + (size_t)zh * g.bSH + (size_t)e * g.bExp;

    // A: fp32, row = f>>4, col4 = f&15 (f = tid + 256*i, i<8)
    const float4* ap[8]; bool aval[8];
#pragma unroll
    for (int i = 0; i < 8; i++) {
        int f = tid + 256 * i, arow = f >> 4, c4 = f & 15;
        long r;
        if (g.arowIdx) { int tk = srow[arow]; aval[i] = (tk >= 0); r = (tk >= 0) ? tk : 0; }
        else { aval[i] = true; r = m0 + arow; }
        ap[i] = (const float4*)(Abase + (size_t)r * g.lda) + c4;
    }
    // B: bf16 hi/lo K-major, row = f>>3 (128 rows), c16 = f&7 (8 uint4 = 64 k)
    const uint4* bp[8];
#pragma unroll
    for (int i = 0; i < 4; i++) {
        int f = tid + 256 * i, brow = f >> 3, c16 = f & 7;
        size_t boff = (size_t)(n0 + brow) * g.ldb + (size_t)c16 * 8;
        bp[i] = (const uint4*)(Bhb + boff);
        bp[i + 4] = (const uint4*)(Blb + boff);
    }

    float4 pa[8]; uint4 pb[8];
    auto loadregs = [&](int kc) {
        size_t oa = (size_t)16 * kc, ob = (size_t)8 * kc;
#pragma unroll
        for (int i = 0; i < 8; i++) pa[i] = aval[i] ? ap[i][oa] : make_float4(0.f, 0.f, 0.f, 0.f);
#pragma unroll
        for (int i = 0; i < 8; i++) pb[i] = bp[i][ob];
    };
    auto sts = [&](int s) {
        char* st = tiles + s * 65536;
#pragma unroll
        for (int i = 0; i < 8; i++) {
            int f = tid + 256 * i, arow = f >> 4, c4 = f & 15;
            int sw = SWZ(arow * 128 + c4 * 8);
            uint2 hi, lo; pack_split(pa[i], hi, lo);
            *(uint2*)(st + sw) = hi;
            *(uint2*)(st + 16384 + sw) = lo;
        }
#pragma unroll
        for (int i = 0; i < 4; i++) {
            int f = tid + 256 * i, brow = f >> 3, c16 = f & 7;
            int sw = SWZ(brow * 128 + c16 * 16);
            *(uint4*)(st + 32768 + sw) = pb[i];
            *(uint4*)(st + 49152 + sw) = pb[i + 4];
        }
    };

    const uint32_t tilesU = s2u(tiles);
    const int wm = wid >> 2, wn = wid & 3;
    const int m_w = wm * 64, n_w = wn * 32;
    const int jj = lid >> 3, rr = lid & 7;

    float acc[4][4][4];
#pragma unroll
    for (int a = 0; a < 4; a++)
#pragma unroll
        for (int b = 0; b < 4; b++)
#pragma unroll
            for (int c = 0; c < 4; c++) acc[a][b][c] = 0.f;

    auto compute = [&](int s) {
        uint32_t base = tilesU + s * 65536;
#pragma unroll
        for (int k16 = 0; k16 < 4; k16++) {
            int kk = k16 * 16;
            uint32_t Ah[4][4], Al[4][4];
#pragma unroll
            for (int mf = 0; mf < 4; mf++) {
                int row = m_w + mf * 16 + (jj & 1) * 8 + rr;
                int kb = (kk + (jj >> 1) * 8) * 2;
                uint32_t off = (uint32_t)(row * 128 + (kb ^ ((row & 7) * 16)));
                ldsm4(Ah[mf], base + off);
                ldsm4(Al[mf], base + 16384 + off);
            }
            uint32_t Bh[2][4], Bl[2][4];
#pragma unroll
            for (int np = 0; np < 2; np++) {
                int row = n_w + np * 16 + (jj >> 1) * 8 + rr;
                int kb = (kk + (jj & 1) * 8) * 2;
                uint32_t off = (uint32_t)(row * 128 + (kb ^ ((row & 7) * 16)));
                ldsm4(Bh[np], base + 32768 + off);
                ldsm4(Bl[np], base + 49152 + off);
            }
            // three sweeps: hh, hl, lh — acc dependency distance = 16 MMAs
#pragma unroll
            for (int pass = 0; pass < 3; pass++)
#pragma unroll
                for (int mf = 0; mf < 4; mf++)
#pragma unroll
                    for (int nf = 0; nf < 4; nf++) {
                        const uint32_t* a = (pass == 2) ? Al[mf] : Ah[mf];
                        const uint32_t* b = (pass == 1) ? &Bl[nf >> 1][(nf & 1) * 2]
                                                        : &Bh[nf >> 1][(nf & 1) * 2];
                        mma16816(acc[mf][nf], a, b);
                    }
        }
    };

    const int nC = g.Kdim >> 6;
    loadregs(0);
    sts(0);
    __syncthreads();
    for (int kc = 0; kc < nC; kc++) {
        if (kc + 1 < nC) loadregs(kc + 1);
        compute(kc & 1);
        if (kc + 1 < nC) {
            sts((kc + 1) & 1);
            __syncthreads();
        }
    }

    // ---------- epilogue ----------
    const float* biasp = g.bias ? (g.bias + (size_t)e * g.biasExp + n0) : (const float*)0;
    size_t cbase = (size_t)zb * g.cSB + (size_t)zh * g.cSH;
#pragma unroll
    for (int mf = 0; mf < 4; mf++) {
#pragma unroll
        for (int half = 0; half < 2; half++) {
            int mrow = m_w + mf * 16 + (lid >> 2) + half * 8;
            long gm = m0 + mrow;
            size_t roff = cbase + (size_t)gm * g.ldc + n0;
#pragma unroll
            for (int nf = 0; nf < 4; nf++) {
                int col = n_w + nf * 8 + (lid & 3) * 2;
                float v0 = acc[mf][nf][half * 2 + 0];
                float v1 = acc[mf][nf][half * 2 + 1];
                if (biasp) { v0 += biasp[col]; v1 += biasp[col + 1]; }
                if (g.relu) { v0 = fmaxf(v0, 0.f); v1 = fmaxf(v1, 0.f); }
                if (g.Ch) {
                    bf16 h0, l0, h1, l1;
                    split2(v0, h0, l0); split2(v1, h1, l1);
                    *(__nv_bfloat162*)(g.Ch + roff + col) = __halves2bfloat162(h0, h1);
                    *(__nv_bfloat162*)(g.Cl + roff + col) = __halves2bfloat162(l0, l1);
                }
                if (g.C) {
                    g.C[roff + col] = v0;
                    g.C[roff + col + 1] = v1;
                }
            }
        }
    }
}

// ---------- weight transpose+split: W[K,N](fp32) -> Wt[N,K] hi/lo ----------
__global__ void wsplit(const float* __restrict__ W, bf16* __restrict__ oh,
                       bf16* __restrict__ ol, int K, int N)
{
    __shared__ float t[32][33];
    size_t zoff = (size_t)blockIdx.z * K * N;
    W += zoff; oh += zoff; ol += zoff;
    int n0 = blockIdx.x * 32, k0 = blockIdx.y * 32;
    int tx = threadIdx.x, ty = threadIdx.y;
#pragma unroll
    for (int r = 0; r < 4; r++)
        t[ty + r * 8][tx] = W[(size_t)(k0 + ty + r * 8) * N + n0 + tx];
    __syncthreads();
#pragma unroll
    for (int r = 0; r < 4; r++) {
        int n = n0 + ty + r * 8, k = k0 + tx;
        bf16 h, l; split2(t[tx][ty + r * 8], h, l);
        oh[(size_t)n * K + k] = h; ol[(size_t)n * K + k] = l;
    }
}

// ---------- V transpose+split: g_v[t][h*128+d] -> Vt[bh][d][m] hi/lo ----------
__global__ void vtsplit()
{
    __shared__ float t[32][33];
    int bh = blockIdx.z, b = bh >> 3, h = bh & 7;
    int m0 = blockIdx.x * 32, d0 = blockIdx.y * 32;
    int tx = threadIdx.x, ty = threadIdx.y;
#pragma unroll
    for (int r = 0; r < 4; r++)
        t[ty + r * 8][tx] = g_v[((size_t)b * NE_ + m0 + ty + r * 8) * O_ + h * HD_ + d0 + tx];
    __syncthreads();
#pragma unroll
    for (int r = 0; r < 4; r++) {
        int d = d0 + ty + r * 8, m = m0 + tx;
        bf16 h2, l2; split2(t[tx][ty + r * 8], h2, l2);
        size_t o = ((size_t)bh * HD_ + d) * NE_ + m;
        g_vth[o] = h2; g_vtl[o] = l2;
    }
}

// ---------- 1) pooling (single pass; also zeroes MoE counters) ----------
__global__ void __launch_bounds__(256) pool_kernel(const float* __restrict__ x,
                                                   const float* __restrict__ attn_w)
{
    const int t = blockIdx.x, tid = threadIdx.x;
    if (t == 0 && tid < E_) { g_cnt[tid] = 0; g_fill[tid] = 0; }
    const float* base = x + (size_t)t * NO_ * D_;
    float4 aw = ((const float4*)attn_w)[tid];
    float4 xv[NO_];
    float p[NO_];
#pragma unroll
    for (int o = 0; o < NO_; o++) {
        xv[o] = ((const float4*)(base + (size_t)o * D_))[tid];
        p[o] = xv[o].x * aw.x + xv[o].y * aw.y + xv[o].z * aw.z + xv[o].w * aw.w;
    }
#pragma unroll
    for (int off = 16; off; off >>= 1)
#pragma unroll
        for (int o = 0; o < NO_; o++) p[o] += __shfl_down_sync(0xffffffffu, p[o], off);
    __shared__ float sm[NO_][8], wsh[NO_];
    const int w = tid >> 5;
    if ((tid & 31) == 0)
#pragma unroll
        for (int o = 0; o < NO_; o++) sm[o][w] = p[o];
    __syncthreads();
    if (tid == 0) {
        float l[NO_];
#pragma unroll
        for (int o = 0; o < NO_; o++) {
            float s = 0.f;
#pragma unroll
            for (int ww = 0; ww < 8; ww++) s += sm[o][ww];
            l[o] = s;
        }
        float mx = l[0];
#pragma unroll
        for (int o = 1; o < NO_; o++) mx = fmaxf(mx, l[o]);
        float ss = 0.f;
#pragma unroll
        for (int o = 0; o < NO_; o++) { float ev = expf(l[o] - mx); wsh[o] = ev; ss += ev; }
        float inv = 1.f / ss;
#pragma unroll
        for (int o = 0; o < NO_; o++) wsh[o] *= inv;
    }
    __syncthreads();
    float4 ov = make_float4(0.f, 0.f, 0.f, 0.f);
#pragma unroll
    for (int o = 0; o < NO_; o++) {
        float wo = wsh[o];
        ov.x = fmaf(wo, xv[o].x, ov.x); ov.y = fmaf(wo, xv[o].y, ov.y);
        ov.z = fmaf(wo, xv[o].z, ov.z); ov.w = fmaf(wo, xv[o].w, ov.w);
    }
    ((float4*)(g_xagg + (size_t)t * D_))[tid] = ov;
}

// ---------- 2a) gating ----------
__global__ void __launch_bounds__(256) gate_kernel(const float* __restrict__ gW,
                                                   const float* __restrict__ gb)
{
    const int t = blockIdx.x, tid = threadIdx.x;
    float4 xv = ((const float4*)(g_xagg + (size_t)t * D_))[tid];
    float xs[4] = {xv.x, xv.y, xv.z, xv.w};
    const float* gr = gW + (size_t)tid * 4 * E_;
    float acc[E_];
#pragma unroll
    for (int e = 0; e < E_; e++) acc[e] = 0.f;
#pragma unroll
    for (int r = 0; r < 4; r++) {
        float4 w0 = *(const float4*)(gr + r * E_);
        float4 w1 = *(const float4*)(gr + r * E_ + 4);
        acc[0] = fmaf(xs[r], w0.x, acc[0]); acc[1] = fmaf(xs[r], w0.y, acc[1]);
        acc[2] = fmaf(xs[r], w0.z, acc[2]); acc[3] = fmaf(xs[r], w0.w, acc[3]);
        acc[4] = fmaf(xs[r], w1.x, acc[4]); acc[5] = fmaf(xs[r], w1.y, acc[5]);
        acc[6] = fmaf(xs[r], w1.z, acc[6]); acc[7] = fmaf(xs[r], w1.w, acc[7]);
    }
#pragma unroll
    for (int off = 16; off; off >>= 1)
#pragma unroll
        for (int e = 0; e < E_; e++) acc[e] += __shfl_down_sync(0xffffffffu, acc[e], off);
    __shared__ float sm[E_][8];
    const int w = tid >> 5;
    if ((tid & 31) == 0)
#pragma unroll
        for (int e = 0; e < E_; e++) sm[e][w] = acc[e];
    __syncthreads();
    if (tid == 0) {
        float l[E_];
#pragma unroll
        for (int e = 0; e < E_; e++) {
            float s = gb[e];
#pragma unroll
            for (int ww = 0; ww < 8; ww++) s += sm[e][ww];
            l[e] = s;
        }
        int i0 = 0;
#pragma unroll
        for (int e = 1; e < E_; e++) if (l[e] > l[i0]) i0 = e;
        int i1 = -1;
#pragma unroll
        for (int e = 0; e < E_; e++) if (e != i0 && (i1 < 0 || l[e] > l[i1])) i1 = e;
        float g0 = 1.f / (1.f + expf(l[i1] - l[i0]));
        g_topi[2 * t] = i0; g_topi[2 * t + 1] = i1;
        g_gate[2 * t] = g0; g_gate[2 * t + 1] = 1.f - g0;
        atomicAdd(&g_cnt[i0], 1); atomicAdd(&g_cnt[i1], 1);
    }
}

// ---------- 2b) scan + slot init ----------
__global__ void scan_kernel()
{
    if (threadIdx.x == 0) {
        int off = 0;
        for (int e = 0; e < E_; e++) {
            g_off[e] = off;
            int tiles = (g_cnt[e] + TM - 1) / TM;
            for (int tt = 0; tt < tiles; tt++) g_tile_e[off / TM + tt] = e;
            off += tiles * TM;
        }
        g_off[E_] = off;
        for (int tt = off / TM; tt < MAXTILES; tt++) g_tile_e[tt] = -1;
    }
    for (int s = threadIdx.x; s < SLOTMAX; s += blockDim.x) g_slot_tok[s] = -1;
}

// ---------- 2c) place ----------
__global__ void place_kernel()
{
    int t = blockIdx.x * blockDim.x + threadIdx.x;
    if (t >= T_) return;
#pragma unroll
    for (int j = 0; j < 2; j++) {
        int e = g_topi[2 * t + j];
        int pos = atomicAdd(&g_fill[e], 1);
        int s = g_off[e] + pos;
        g_slot_tok[s] = t;
        g_tok_slot[2 * t + j] = s;
    }
}

// ---------- 2f) combine ----------
__global__ void __launch_bounds__(256) combine_kernel(const float* __restrict__ buf)
{
    const int t = blockIdx.x, tid = threadIdx.x;
    int s0 = g_tok_slot[2 * t], s1 = g_tok_slot[2 * t + 1];
    float w0 = g_gate[2 * t], w1 = g_gate[2 * t + 1];
    float4 a = ((const float4*)(buf + (size_t)s0 * O_))[tid];
    float4 b = ((const float4*)(buf + (size_t)s1 * O_))[tid];
    float4 o;
    o.x = w0 * a.x + w1 * b.x; o.y = w0 * a.y + w1 * b.y;
    o.z = w0 * a.z + w1 * b.z; o.w = w0 * a.w + w1 * b.w;
    ((float4*)(g_ent + (size_t)t * O_))[tid] = o;
}

// ---------- 3b) softmax ----------
__global__ void __launch_bounds__(256) attn_softmax_kernel()
{
    const int tid = threadIdx.x;
    float* row = g_scores + (size_t)blockIdx.x * NE_;
    float4 v = ((float4*)row)[tid];
    const float sc = 0.08838834764831845f;
    v.x *= sc; v.y *= sc; v.z *= sc; v.w *= sc;
    float m = fmaxf(fmaxf(v.x, v.y), fmaxf(v.z, v.w));
#pragma unroll
    for (int off = 16; off; off >>= 1) m = fmaxf(m, __shfl_xor_sync(0xffffffffu, m, off));
    __shared__ float sr[8];
    const int w = tid >> 5;
    if ((tid & 31) == 0) sr[w] = m;
    __syncthreads();
    float gm = sr[0];
#pragma unroll
    for (int i = 1; i < 8; i++) gm = fmaxf(gm, sr[i]);
    float e0 = expf(v.x - gm), e1 = expf(v.y - gm), e2 = expf(v.z - gm), e3 = expf(v.w - gm);
    float s = e0 + e1 + e2 + e3;
#pragma unroll
    for (int off = 16; off; off >>= 1) s += __shfl_xor_sync(0xffffffffu, s, off);
    __syncthreads();
    if ((tid & 31) == 0) sr[w] = s;
    __syncthreads();
    float gs = 0.f;
#pragma unroll
    for (int i = 0; i < 8; i++) gs += sr[i];
    float inv = 1.f / gs;
    ((float4*)row)[tid] = make_float4(e0 * inv, e1 * inv, e2 * inv, e3 * inv);
}

// ---------- host ----------
#define SYM(p, s) do { void* _t; cudaGetSymbolAddress(&_t, s); p = (decltype(p))_t; } while (0)

static GArgs ga(const float* A, long lda, const bf16* Bh, const bf16* Bl, long ldb,
                float* C, long ldc, int Kdim, const float* bias)
{
    GArgs g = {};
    g.A = A; g.lda = lda; g.Bh = Bh; g.Bl = Bl; g.ldb = ldb;
    g.C = C; g.ldc = ldc; g.Kdim = Kdim; g.bias = bias;
    return g;
}

extern "C" void kernel_launch(void* const* d_in, const int* in_sizes, int n_in,
                              void* d_out, int out_size)
{
    const float* x      = (const float*)d_in[0];
    const float* attn_w = (const float*)d_in[1];
    const float* gate_W = (const float*)d_in[2];
    const float* gate_b = (const float*)d_in[3];
    const float* eW1 = (const float*)d_in[4];
    const float* eb1 = (const float*)d_in[5];
    const float* eW2 = (const float*)d_in[6];
    const float* eb2 = (const float*)d_in[7];
    const float* Wq = (const float*)d_in[8];
    const float* bq = (const float*)d_in[9];
    const float* Wk = (const float*)d_in[10];
    const float* bk = (const float*)d_in[11];
    const float* Wv = (const float*)d_in[12];
    const float* bv = (const float*)d_in[13];
    const float* Wo = (const float*)d_in[14];
    const float* bo = (const float*)d_in[15];
    const float* fW1 = (const float*)d_in[16];
    const float* fb1 = (const float*)d_in[17];
    const float* fW2 = (const float*)d_in[18];
    const float* fb2 = (const float*)d_in[19];
    float* out = (float*)d_out;

    float *p_xagg, *p_ent, *p_hbuf, *p_q, *p_v, *p_scores, *p_ctx, *p_rel;
    int *p_slot_tok, *p_tile_e;
    bf16 *p_eW1h, *p_eW1l, *p_eW2h, *p_eW2l, *p_Wqh, *p_Wql, *p_Wkh, *p_Wkl;
    bf16 *p_Wvh, *p_Wvl, *p_Woh, *p_Wol, *p_fW1h, *p_fW1l, *p_fW2h, *p_fW2l;
    bf16 *p_kh, *p_kl, *p_vth, *p_vtl;
    SYM(p_xagg, g_xagg); SYM(p_ent, g_ent); SYM(p_hbuf, g_hbuf);
    SYM(p_q, g_q); SYM(p_v, g_v);
    SYM(p_scores, g_scores); SYM(p_ctx, g_ctx); SYM(p_rel, g_rel);
    SYM(p_slot_tok, g_slot_tok); SYM(p_tile_e, g_tile_e);
    SYM(p_eW1h, g_eW1h); SYM(p_eW1l, g_eW1l); SYM(p_eW2h, g_eW2h); SYM(p_eW2l, g_eW2l);
    SYM(p_Wqh, g_Wqh); SYM(p_Wql, g_Wql); SYM(p_Wkh, g_Wkh); SYM(p_Wkl, g_Wkl);
    SYM(p_Wvh, g_Wvh); SYM(p_Wvl, g_Wvl); SYM(p_Woh, g_Woh); SYM(p_Wol, g_Wol);
    SYM(p_fW1h, g_fW1h); SYM(p_fW1l, g_fW1l); SYM(p_fW2h, g_fW2h); SYM(p_fW2l, g_fW2l);
    SYM(p_kh, g_kh); SYM(p_kl, g_kl); SYM(p_vth, g_vth); SYM(p_vtl, g_vtl);
    float* p_moebuf = p_scores;

    cudaFuncSetAttribute(tc_gemm, cudaFuncAttributeMaxDynamicSharedMemorySize, TC_SMEM);
    dim3 tb(32, 8);

    pool_kernel<<<T_, 256>>>(x, attn_w);                       // 1
    gate_kernel<<<T_, 256>>>(gate_W, gate_b);                  // 2
    scan_kernel<<<1, 256>>>();                                 // 3
    place_kernel<<<(T_ + 255) / 256, 256>>>();                 // 4
    wsplit<<<dim3(H_ / 32, D_ / 32, E_), tb>>>(eW1, p_eW1h, p_eW1l, D_, H_);  // 5
    // MoE expert GEMM 1                                        // 6 <- profiled
    {
        GArgs g = ga(p_xagg, D_, p_eW1h, p_eW1l, D_, p_hbuf, H_, D_, eb1);
        g.biasExp = (long)H_; g.relu = 1; g.arowIdx = p_slot_tok; g.tileE = p_tile_e;
        g.bExp = (long)D_ * H_;
        tc_gemm<<<dim3(H_ / TN, MAXTILES), 256, TC_SMEM>>>(g);
    }
    wsplit<<<dim3(O_ / 32, H_ / 32, E_), tb>>>(eW2, p_eW2h, p_eW2l, H_, O_);
    {
        GArgs g = ga(p_hbuf, H_, p_eW2h, p_eW2l, H_, p_moebuf, O_, H_, eb2);
        g.biasExp = (long)O_; g.tileE = p_tile_e; g.bExp = (long)H_ * O_;
        tc_gemm<<<dim3(O_ / TN, MAXTILES), 256, TC_SMEM>>>(g);
    }
    combine_kernel<<<T_, 256>>>(p_moebuf);
    // QKV projections
    wsplit<<<dim3(O_ / 32, O_ / 32, 1), tb>>>(Wq, p_Wqh, p_Wql, O_, O_);
    tc_gemm<<<dim3(O_ / TN, T_ / TM), 256, TC_SMEM>>>(ga(p_ent, O_, p_Wqh, p_Wql, O_, p_q, O_, O_, bq));
    wsplit<<<dim3(O_ / 32, O_ / 32, 1), tb>>>(Wk, p_Wkh, p_Wkl, O_, O_);
    {
        GArgs g = ga(p_ent, O_, p_Wkh, p_Wkl, O_, (float*)0, O_, O_, bk);
        g.Ch = p_kh; g.Cl = p_kl;
        tc_gemm<<<dim3(O_ / TN, T_ / TM), 256, TC_SMEM>>>(g);
    }
    wsplit<<<dim3(O_ / 32, O_ / 32, 1), tb>>>(Wv, p_Wvh, p_Wvl, O_, O_);
    tc_gemm<<<dim3(O_ / TN, T_ / TM), 256, TC_SMEM>>>(ga(p_ent, O_, p_Wvh, p_Wvl, O_, p_v, O_, O_, bv));
    vtsplit<<<dim3(NE_ / 32, HD_ / 32, B_ * NH_), tb>>>();
    // scores = q @ k^T (B = kh/kl rows, K-major)
    {
        GArgs g = ga(p_q, O_, p_kh, p_kl, O_, p_scores, NE_, HD_, 0);
        g.aSB = (long)NE_ * O_; g.aSH = HD_;
        g.bSB = (long)NE_ * O_; g.bSH = HD_;
        g.cSB = (long)NH_ * NE_ * NE_; g.cSH = (long)NE_ * NE_;
        tc_gemm<<<dim3(NE_ / TN, NE_ / TM, B_ * NH_), 256, TC_SMEM>>>(g);
    }
    attn_softmax_kernel<<<B_ * NH_ * NE_, 256>>>();
    // ctx = attn @ v (B = Vt[bh][d][m], K-major)
    {
        GArgs g = ga(p_scores, NE_, p_vth, p_vtl, NE_, p_ctx, O_, NE_, 0);
        g.aSB = (long)NH_ * NE_ * NE_; g.aSH = (long)NE_ * NE_;
        g.bSB = (long)NH_ * HD_ * NE_; g.bSH = (long)HD_ * NE_;
        g.cSB = (long)NE_ * O_; g.cSH = HD_;
        tc_gemm<<<dim3(1, NE_ / TM, B_ * NH_), 256, TC_SMEM>>>(g);
    }
    // Wo + FFN
    wsplit<<<dim3(O_ / 32, O_ / 32, 1), tb>>>(Wo, p_Woh, p_Wol, O_, O_);
    tc_gemm<<<dim3(O_ / TN, T_ / TM), 256, TC_SMEM>>>(ga(p_ctx, O_, p_Woh, p_Wol, O_, p_rel, O_, O_, bo));
    wsplit<<<dim3(FH_ / 32, O_ / 32, 1), tb>>>(fW1, p_fW1h, p_fW1l, O_, FH_);
    {
        GArgs g = ga(p_rel, O_, p_fW1h, p_fW1l, O_, p_hbuf, FH_, O_, fb1);
        g.relu = 1;
        tc_gemm<<<dim3(FH_ / TN, T_ / TM), 256, TC_SMEM>>>(g);
    }
    wsplit<<<dim3(O_ / 32, FH_ / 32, 1), tb>>>(fW2, p_fW2h, p_fW2l, FH_, O_);
    tc_gemm<<<dim3(O_ / TN, T_ / TM), 256, TC_SMEM>>>(ga(p_hbuf, FH_, p_fW2h, p_fW2l, FH_, out, O_, FH_, fb2));
}

// round 12
// speedup vs baseline: 1.0437x; 1.0437x over previous
#include <cuda_runtime.h>
#include <cuda_bf16.h>
#include <math.h>
#include <stdint.h>

#define B_ 8
#define NE_ 1024
#define NO_ 8
#define D_ 1024
#define E_ 8
#define H_ 2048
#define O_ 1024
#define NH_ 8
#define HD_ 128
#define FH_ 4096
#define T_ 8192
#define QKV_ (3 * O_)
#define TM 128
#define TN 128
#define MAXTILES 136
#define SLOTMAX (MAXTILES * TM)

typedef __nv_bfloat16 bf16;

// ---------- device scratch ----------
__device__ float g_xagg[(size_t)T_ * D_];                    // fp32 for gate
__device__ int   g_topi[T_ * 2];
__device__ float g_gate[T_ * 2];
__device__ int   g_cnt[E_], g_off[E_ + 1], g_fill[E_];
__device__ int   g_tile_e[MAXTILES];
__device__ int   g_slot_tok[SLOTMAX];
__device__ int   g_tok_slot[T_ * 2];
__device__ float g_scores[(size_t)B_ * NH_ * NE_ * NE_];     // fp32 scores; also MoE slot buf
__device__ float g_bqkv[QKV_];
// split bf16 activations
__device__ bf16 g_xaggh[(size_t)T_ * D_],  g_xaggl[(size_t)T_ * D_];
__device__ bf16 g_enth[(size_t)T_ * O_],   g_entl[(size_t)T_ * O_];
__device__ bf16 g_hbufh[(size_t)SLOTMAX * H_], g_hbufl[(size_t)SLOTMAX * H_]; // also ffn hidden
__device__ bf16 g_qkvh[(size_t)T_ * QKV_], g_qkvl[(size_t)T_ * QKV_];
__device__ bf16 g_atth[(size_t)B_ * NH_ * NE_ * NE_], g_attl[(size_t)B_ * NH_ * NE_ * NE_];
__device__ bf16 g_ctxh[(size_t)T_ * O_],   g_ctxl[(size_t)T_ * O_];
__device__ bf16 g_relh[(size_t)T_ * O_],   g_rell[(size_t)T_ * O_];
__device__ bf16 g_vth[(size_t)B_ * NH_ * HD_ * NE_], g_vtl[(size_t)B_ * NH_ * HD_ * NE_];
// split transposed weights Wt[N][K]
__device__ bf16 g_eW1h[(size_t)E_ * D_ * H_], g_eW1l[(size_t)E_ * D_ * H_];
__device__ bf16 g_eW2h[(size_t)E_ * H_ * O_], g_eW2l[(size_t)E_ * H_ * O_];
__device__ bf16 g_Wqkvh[(size_t)QKV_ * O_], g_Wqkvl[(size_t)QKV_ * O_];
__device__ bf16 g_Woh[(size_t)O_ * O_], g_Wol[(size_t)O_ * O_];
__device__ bf16 g_fW1h[(size_t)O_ * FH_], g_fW1l[(size_t)O_ * FH_];
__device__ bf16 g_fW2h[(size_t)FH_ * O_], g_fW2l[(size_t)FH_ * O_];

// ---------- helpers ----------
#define SWZ(o) ((o) ^ (((o) >> 3) & 0x70))

__device__ __forceinline__ uint32_t s2u(const void* p) {
    uint32_t a;
    asm("{ .reg .u64 t; cvta.to.shared.u64 t, %1; cvt.u32.u64 %0, t; }" : "=r"(a) : "l"(p));
    return a;
}
__device__ __forceinline__ void split2(float v, bf16& h, bf16& l) {
    h = __float2bfloat16(v);
    l = __float2bfloat16(v - __bfloat162float(h));
}
__device__ __forceinline__ void ldsm4(uint32_t* r, uint32_t addr) {
    asm volatile("ldmatrix.sync.aligned.m8n8.x4.shared.b16 {%0,%1,%2,%3}, [%4];"
                 : "=r"(r[0]), "=r"(r[1]), "=r"(r[2]), "=r"(r[3]) : "r"(addr));
}
__device__ __forceinline__ void mma16816(float* c, const uint32_t* a, const uint32_t* b) {
    asm volatile("mma.sync.aligned.m16n8k16.row.col.f32.bf16.bf16.f32 "
                 "{%0,%1,%2,%3}, {%4,%5,%6,%7}, {%8,%9}, {%0,%1,%2,%3};"
                 : "+f"(c[0]), "+f"(c[1]), "+f"(c[2]), "+f"(c[3])
                 : "r"(a[0]), "r"(a[1]), "r"(a[2]), "r"(a[3]), "r"(b[0]), "r"(b[1]));
}
__device__ __forceinline__ void pack_split(float4 v, uint2& hi, uint2& lo) {
    bf16 h0, l0, h1, l1, h2, l2, h3, l3;
    split2(v.x, h0, l0); split2(v.y, h1, l1);
    split2(v.z, h2, l2); split2(v.w, h3, l3);
    __nv_bfloat162 hA = __halves2bfloat162(h0, h1), hB = __halves2bfloat162(h2, h3);
    __nv_bfloat162 lA = __halves2bfloat162(l0, l1), lB = __halves2bfloat162(l2, l3);
    hi = make_uint2(*(uint32_t*)&hA, *(uint32_t*)&hB);
    lo = make_uint2(*(uint32_t*)&lA, *(uint32_t*)&lB);
}

struct GArgs {
    const bf16 *Ah, *Al; long lda, aSB, aSH;
    const bf16 *Bh, *Bl; long ldb, bSB, bSH, bExp;   // B[N][K] K-major
    float* C; long ldc, cSB, cSH;
    bf16 *Ch, *Cl;                                   // optional split bf16 output
    const float* bias; long biasExp;
    const int* arowIdx; const int* tileE;
    int Kdim, relu;
};

#define TC_SMEM 133120   // 2048 ctrl + 2 * 65536 stages

// ---------- all-bf16-split tensor-core GEMM (mma.sync), pure-copy producers ----------
// CTA 128x128, KC=64, 8 warps (2x4), double-buffered.
__global__ void __launch_bounds__(256, 1) tc_gemm(GArgs g)
{
    int e = 0;
    if (g.tileE) { e = g.tileE[blockIdx.y]; if (e < 0) return; }
    extern __shared__ char smem[];
    char* tiles = (char*)((((uintptr_t)smem) + 1024 + 1023) & ~(uintptr_t)1023);
    const int tid = threadIdx.x, wid = tid >> 5, lid = tid & 31;
    int* srow = (int*)smem;
    const long m0 = (long)blockIdx.y * TM, n0 = (long)blockIdx.x * TN;
    const int z = blockIdx.z, zb = z >> 3, zh = z & 7;

    if (g.arowIdx && tid < TM) srow[tid] = g.arowIdx[m0 + tid];
    __syncthreads();

    const bf16* Ahb = g.Ah + (size_t)zb * g.aSB + (size_t)zh * g.aSH;
    const bf16* Alb = g.Al + (size_t)zb * g.aSB + (size_t)zh * g.aSH;
    const bf16* Bhb = g.Bh + (size_t)zb * g.bSB + (size_t)zh * g.bSH + (size_t)e * g.bExp;
    const bf16* Blb = g.Bl + (size_t)zb * g.bSB + (size_t)zh * g.bSH + (size_t)e * g.bExp;

    // A: bf16 hi/lo, row = f>>3 (128 rows), c16 = f&7 (8 uint4 = 64 k)
    const uint4 *ahp[4], *alp[4]; bool aval[4];
#pragma unroll
    for (int i = 0; i < 4; i++) {
        int f = tid + 256 * i, arow = f >> 3, c16 = f & 7;
        long r;
        if (g.arowIdx) { int tk = srow[arow]; aval[i] = (tk >= 0); r = (tk >= 0) ? tk : 0; }
        else { aval[i] = true; r = m0 + arow; }
        size_t off = (size_t)r * g.lda + (size_t)c16 * 8;
        ahp[i] = (const uint4*)(Ahb + off);
        alp[i] = (const uint4*)(Alb + off);
    }
    // B: bf16 hi/lo, same shape
    const uint4* bp[8];
#pragma unroll
    for (int i = 0; i < 4; i++) {
        int f = tid + 256 * i, brow = f >> 3, c16 = f & 7;
        size_t boff = (size_t)(n0 + brow) * g.ldb + (size_t)c16 * 8;
        bp[i] = (const uint4*)(Bhb + boff);
        bp[i + 4] = (const uint4*)(Blb + boff);
    }

    uint4 pa[8], pb[8];
    const uint4 z4 = make_uint4(0u, 0u, 0u, 0u);
    auto loadregs = [&](int kc) {
        size_t o = (size_t)8 * kc;
#pragma unroll
        for (int i = 0; i < 4; i++) {
            pa[i]     = aval[i] ? ahp[i][o] : z4;
            pa[i + 4] = aval[i] ? alp[i][o] : z4;
        }
#pragma unroll
        for (int i = 0; i < 8; i++) pb[i] = bp[i][o];
    };
    auto sts = [&](int s) {
        char* st = tiles + s * 65536;
#pragma unroll
        for (int i = 0; i < 4; i++) {
            int f = tid + 256 * i, arow = f >> 3, c16 = f & 7;
            int sw = SWZ(arow * 128 + c16 * 16);
            *(uint4*)(st + sw)         = pa[i];
            *(uint4*)(st + 16384 + sw) = pa[i + 4];
        }
#pragma unroll
        for (int i = 0; i < 4; i++) {
            int f = tid + 256 * i, brow = f >> 3, c16 = f & 7;
            int sw = SWZ(brow * 128 + c16 * 16);
            *(uint4*)(st + 32768 + sw) = pb[i];
            *(uint4*)(st + 49152 + sw) = pb[i + 4];
        }
    };

    const uint32_t tilesU = s2u(tiles);
    const int wm = wid >> 2, wn = wid & 3;
    const int m_w = wm * 64, n_w = wn * 32;
    const int jj = lid >> 3, rr = lid & 7;

    float acc[4][4][4];
#pragma unroll
    for (int a = 0; a < 4; a++)
#pragma unroll
        for (int b = 0; b < 4; b++)
#pragma unroll
            for (int c = 0; c < 4; c++) acc[a][b][c] = 0.f;

    auto compute = [&](int s) {
        uint32_t base = tilesU + s * 65536;
#pragma unroll
        for (int k16 = 0; k16 < 4; k16++) {
            int kk = k16 * 16;
            uint32_t Ah[4][4], Al[4][4];
#pragma unroll
            for (int mf = 0; mf < 4; mf++) {
                int row = m_w + mf * 16 + (jj & 1) * 8 + rr;
                int kb = (kk + (jj >> 1) * 8) * 2;
                uint32_t off = (uint32_t)(row * 128 + (kb ^ ((row & 7) * 16)));
                ldsm4(Ah[mf], base + off);
                ldsm4(Al[mf], base + 16384 + off);
            }
            uint32_t Bh[2][4], Bl[2][4];
#pragma unroll
            for (int np = 0; np < 2; np++) {
                int row = n_w + np * 16 + (jj >> 1) * 8 + rr;
                int kb = (kk + (jj & 1) * 8) * 2;
                uint32_t off = (uint32_t)(row * 128 + (kb ^ ((row & 7) * 16)));
                ldsm4(Bh[np], base + 32768 + off);
                ldsm4(Bl[np], base + 49152 + off);
            }
#pragma unroll
            for (int pass = 0; pass < 3; pass++)
#pragma unroll
                for (int mf = 0; mf < 4; mf++)
#pragma unroll
                    for (int nf = 0; nf < 4; nf++) {
                        const uint32_t* a = (pass == 2) ? Al[mf] : Ah[mf];
                        const uint32_t* b = (pass == 1) ? &Bl[nf >> 1][(nf & 1) * 2]
                                                        : &Bh[nf >> 1][(nf & 1) * 2];
                        mma16816(acc[mf][nf], a, b);
                    }
        }
    };

    const int nC = g.Kdim >> 6;
    loadregs(0);
    sts(0);
    __syncthreads();
    for (int kc = 0; kc < nC; kc++) {
        if (kc + 1 < nC) loadregs(kc + 1);
        compute(kc & 1);
        if (kc + 1 < nC) {
            sts((kc + 1) & 1);
            __syncthreads();
        }
    }

    // ---------- epilogue ----------
    const float* biasp = g.bias ? (g.bias + (size_t)e * g.biasExp + n0) : (const float*)0;
    size_t cbase = (size_t)zb * g.cSB + (size_t)zh * g.cSH;
#pragma unroll
    for (int mf = 0; mf < 4; mf++) {
#pragma unroll
        for (int half = 0; half < 2; half++) {
            int mrow = m_w + mf * 16 + (lid >> 2) + half * 8;
            long gm = m0 + mrow;
            size_t roff = cbase + (size_t)gm * g.ldc + n0;
#pragma unroll
            for (int nf = 0; nf < 4; nf++) {
                int col = n_w + nf * 8 + (lid & 3) * 2;
                float v0 = acc[mf][nf][half * 2 + 0];
                float v1 = acc[mf][nf][half * 2 + 1];
                if (biasp) { v0 += biasp[col]; v1 += biasp[col + 1]; }
                if (g.relu) { v0 = fmaxf(v0, 0.f); v1 = fmaxf(v1, 0.f); }
                if (g.Ch) {
                    bf16 h0, l0, h1, l1;
                    split2(v0, h0, l0); split2(v1, h1, l1);
                    *(__nv_bfloat162*)(g.Ch + roff + col) = __halves2bfloat162(h0, h1);
                    *(__nv_bfloat162*)(g.Cl + roff + col) = __halves2bfloat162(l0, l1);
                }
                if (g.C) {
                    g.C[roff + col] = v0;
                    g.C[roff + col + 1] = v1;
                }
            }
        }
    }
}

// ---------- weight transpose+split: W[K,N](fp32) -> Wt[N,K] hi/lo ----------
__global__ void wsplit(const float* __restrict__ W, bf16* __restrict__ oh,
                       bf16* __restrict__ ol, int K, int N)
{
    __shared__ float t[32][33];
    size_t zoff = (size_t)blockIdx.z * K * N;
    W += zoff; oh += zoff; ol += zoff;
    int n0 = blockIdx.x * 32, k0 = blockIdx.y * 32;
    int tx = threadIdx.x, ty = threadIdx.y;
#pragma unroll
    for (int r = 0; r < 4; r++)
        t[ty + r * 8][tx] = W[(size_t)(k0 + ty + r * 8) * N + n0 + tx];
    __syncthreads();
#pragma unroll
    for (int r = 0; r < 4; r++) {
        int n = n0 + ty + r * 8, k = k0 + tx;
        bf16 h, l; split2(t[tx][ty + r * 8], h, l);
        oh[(size_t)n * K + k] = h; ol[(size_t)n * K + k] = l;
    }
}

// ---------- V transpose (already split): qkv v-section -> Vt[bh][d][m] ----------
__global__ void vtsplit()
{
    __shared__ unsigned short th[32][33], tl[32][33];
    int bh = blockIdx.z, b = bh >> 3, h = bh & 7;
    int m0 = blockIdx.x * 32, d0 = blockIdx.y * 32;
    int tx = threadIdx.x, ty = threadIdx.y;
#pragma unroll
    for (int r = 0; r < 4; r++) {
        size_t src = ((size_t)b * NE_ + m0 + ty + r * 8) * QKV_ + 2 * O_ + h * HD_ + d0 + tx;
        th[ty + r * 8][tx] = *(const unsigned short*)&g_qkvh[src];
        tl[ty + r * 8][tx] = *(const unsigned short*)&g_qkvl[src];
    }
    __syncthreads();
#pragma unroll
    for (int r = 0; r < 4; r++) {
        int d = d0 + ty + r * 8, m = m0 + tx;
        size_t o = ((size_t)bh * HD_ + d) * NE_ + m;
        *(unsigned short*)&g_vth[o] = th[tx][ty + r * 8];
        *(unsigned short*)&g_vtl[o] = tl[tx][ty + r * 8];
    }
}

// ---------- bias concat for fused QKV ----------
__global__ void bcat(const float* __restrict__ bq, const float* __restrict__ bk,
                     const float* __restrict__ bv)
{
    int i = blockIdx.x * 256 + threadIdx.x;
    if (i < O_) {
        g_bqkv[i] = bq[i];
        g_bqkv[O_ + i] = bk[i];
        g_bqkv[2 * O_ + i] = bv[i];
    }
}

// ---------- 1) pooling (single pass; fp32 + split out; zeroes MoE counters) ----------
__global__ void __launch_bounds__(256) pool_kernel(const float* __restrict__ x,
                                                   const float* __restrict__ attn_w)
{
    const int t = blockIdx.x, tid = threadIdx.x;
    if (t == 0 && tid < E_) { g_cnt[tid] = 0; g_fill[tid] = 0; }
    const float* base = x + (size_t)t * NO_ * D_;
    float4 aw = ((const float4*)attn_w)[tid];
    float4 xv[NO_];
    float p[NO_];
#pragma unroll
    for (int o = 0; o < NO_; o++) {
        xv[o] = ((const float4*)(base + (size_t)o * D_))[tid];
        p[o] = xv[o].x * aw.x + xv[o].y * aw.y + xv[o].z * aw.z + xv[o].w * aw.w;
    }
#pragma unroll
    for (int off = 16; off; off >>= 1)
#pragma unroll
        for (int o = 0; o < NO_; o++) p[o] += __shfl_down_sync(0xffffffffu, p[o], off);
    __shared__ float sm[NO_][8], wsh[NO_];
    const int w = tid >> 5;
    if ((tid & 31) == 0)
#pragma unroll
        for (int o = 0; o < NO_; o++) sm[o][w] = p[o];
    __syncthreads();
    if (tid == 0) {
        float l[NO_];
#pragma unroll
        for (int o = 0; o < NO_; o++) {
            float s = 0.f;
#pragma unroll
            for (int ww = 0; ww < 8; ww++) s += sm[o][ww];
            l[o] = s;
        }
        float mx = l[0];
#pragma unroll
        for (int o = 1; o < NO_; o++) mx = fmaxf(mx, l[o]);
        float ss = 0.f;
#pragma unroll
        for (int o = 0; o < NO_; o++) { float ev = expf(l[o] - mx); wsh[o] = ev; ss += ev; }
        float inv = 1.f / ss;
#pragma unroll
        for (int o = 0; o < NO_; o++) wsh[o] *= inv;
    }
    __syncthreads();
    float4 ov = make_float4(0.f, 0.f, 0.f, 0.f);
#pragma unroll
    for (int o = 0; o < NO_; o++) {
        float wo = wsh[o];
        ov.x = fmaf(wo, xv[o].x, ov.x); ov.y = fmaf(wo, xv[o].y, ov.y);
        ov.z = fmaf(wo, xv[o].z, ov.z); ov.w = fmaf(wo, xv[o].w, ov.w);
    }
    ((float4*)(g_xagg + (size_t)t * D_))[tid] = ov;
    uint2 hi, lo; pack_split(ov, hi, lo);
    ((uint2*)(g_xaggh + (size_t)t * D_))[tid] = hi;
    ((uint2*)(g_xaggl + (size_t)t * D_))[tid] = lo;
}

// ---------- 2a) gating ----------
__global__ void __launch_bounds__(256) gate_kernel(const float* __restrict__ gW,
                                                   const float* __restrict__ gb)
{
    const int t = blockIdx.x, tid = threadIdx.x;
    float4 xv = ((const float4*)(g_xagg + (size_t)t * D_))[tid];
    float xs[4] = {xv.x, xv.y, xv.z, xv.w};
    const float* gr = gW + (size_t)tid * 4 * E_;
    float acc[E_];
#pragma unroll
    for (int e = 0; e < E_; e++) acc[e] = 0.f;
#pragma unroll
    for (int r = 0; r < 4; r++) {
        float4 w0 = *(const float4*)(gr + r * E_);
        float4 w1 = *(const float4*)(gr + r * E_ + 4);
        acc[0] = fmaf(xs[r], w0.x, acc[0]); acc[1] = fmaf(xs[r], w0.y, acc[1]);
        acc[2] = fmaf(xs[r], w0.z, acc[2]); acc[3] = fmaf(xs[r], w0.w, acc[3]);
        acc[4] = fmaf(xs[r], w1.x, acc[4]); acc[5] = fmaf(xs[r], w1.y, acc[5]);
        acc[6] = fmaf(xs[r], w1.z, acc[6]); acc[7] = fmaf(xs[r], w1.w, acc[7]);
    }
#pragma unroll
    for (int off = 16; off; off >>= 1)
#pragma unroll
        for (int e = 0; e < E_; e++) acc[e] += __shfl_down_sync(0xffffffffu, acc[e], off);
    __shared__ float sm[E_][8];
    const int w = tid >> 5;
    if ((tid & 31) == 0)
#pragma unroll
        for (int e = 0; e < E_; e++) sm[e][w] = acc[e];
    __syncthreads();
    if (tid == 0) {
        float l[E_];
#pragma unroll
        for (int e = 0; e < E_; e++) {
            float s = gb[e];
#pragma unroll
            for (int ww = 0; ww < 8; ww++) s += sm[e][ww];
            l[e] = s;
        }
        int i0 = 0;
#pragma unroll
        for (int e = 1; e < E_; e++) if (l[e] > l[i0]) i0 = e;
        int i1 = -1;
#pragma unroll
        for (int e = 0; e < E_; e++) if (e != i0 && (i1 < 0 || l[e] > l[i1])) i1 = e;
        float g0 = 1.f / (1.f + expf(l[i1] - l[i0]));
        g_topi[2 * t] = i0; g_topi[2 * t + 1] = i1;
        g_gate[2 * t] = g0; g_gate[2 * t + 1] = 1.f - g0;
        atomicAdd(&g_cnt[i0], 1); atomicAdd(&g_cnt[i1], 1);
    }
}

// ---------- 2b) scan + slot init ----------
__global__ void scan_kernel()
{
    if (threadIdx.x == 0) {
        int off = 0;
        for (int e = 0; e < E_; e++) {
            g_off[e] = off;
            int tiles = (g_cnt[e] + TM - 1) / TM;
            for (int tt = 0; tt < tiles; tt++) g_tile_e[off / TM + tt] = e;
            off += tiles * TM;
        }
        g_off[E_] = off;
        for (int tt = off / TM; tt < MAXTILES; tt++) g_tile_e[tt] = -1;
    }
    for (int s = threadIdx.x; s < SLOTMAX; s += blockDim.x) g_slot_tok[s] = -1;
}

// ---------- 2c) place ----------
__global__ void place_kernel()
{
    int t = blockIdx.x * blockDim.x + threadIdx.x;
    if (t >= T_) return;
#pragma unroll
    for (int j = 0; j < 2; j++) {
        int e = g_topi[2 * t + j];
        int pos = atomicAdd(&g_fill[e], 1);
        int s = g_off[e] + pos;
        g_slot_tok[s] = t;
        g_tok_slot[2 * t + j] = s;
    }
}

// ---------- 2f) combine: ent = g0*buf[s0] + g1*buf[s1], emit split ----------
__global__ void __launch_bounds__(256) combine_kernel(const float* __restrict__ buf)
{
    const int t = blockIdx.x, tid = threadIdx.x;
    int s0 = g_tok_slot[2 * t], s1 = g_tok_slot[2 * t + 1];
    float w0 = g_gate[2 * t], w1 = g_gate[2 * t + 1];
    float4 a = ((const float4*)(buf + (size_t)s0 * O_))[tid];
    float4 b = ((const float4*)(buf + (size_t)s1 * O_))[tid];
    float4 o;
    o.x = w0 * a.x + w1 * b.x; o.y = w0 * a.y + w1 * b.y;
    o.z = w0 * a.z + w1 * b.z; o.w = w0 * a.w + w1 * b.w;
    uint2 hi, lo; pack_split(o, hi, lo);
    ((uint2*)(g_enth + (size_t)t * O_))[tid] = hi;
    ((uint2*)(g_entl + (size_t)t * O_))[tid] = lo;
}

// ---------- 3b) softmax: fp32 scores -> split bf16 attn ----------
__global__ void __launch_bounds__(256) attn_softmax_kernel()
{
    const int tid = threadIdx.x;
    const size_t row = (size_t)blockIdx.x * NE_;
    float4 v = ((const float4*)(g_scores + row))[tid];
    const float sc = 0.08838834764831845f;
    v.x *= sc; v.y *= sc; v.z *= sc; v.w *= sc;
    float m = fmaxf(fmaxf(v.x, v.y), fmaxf(v.z, v.w));
#pragma unroll
    for (int off = 16; off; off >>= 1) m = fmaxf(m, __shfl_xor_sync(0xffffffffu, m, off));
    __shared__ float sr[8];
    const int w = tid >> 5;
    if ((tid & 31) == 0) sr[w] = m;
    __syncthreads();
    float gm = sr[0];
#pragma unroll
    for (int i = 1; i < 8; i++) gm = fmaxf(gm, sr[i]);
    float e0 = expf(v.x - gm), e1 = expf(v.y - gm), e2 = expf(v.z - gm), e3 = expf(v.w - gm);
    float s = e0 + e1 + e2 + e3;
#pragma unroll
    for (int off = 16; off; off >>= 1) s += __shfl_xor_sync(0xffffffffu, s, off);
    __syncthreads();
    if ((tid & 31) == 0) sr[w] = s;
    __syncthreads();
    float gs = 0.f;
#pragma unroll
    for (int i = 0; i < 8; i++) gs += sr[i];
    float inv = 1.f / gs;
    float4 p = make_float4(e0 * inv, e1 * inv, e2 * inv, e3 * inv);
    uint2 hi, lo; pack_split(p, hi, lo);
    ((uint2*)(g_atth + row))[tid] = hi;
    ((uint2*)(g_attl + row))[tid] = lo;
}

// ---------- host ----------
#define SYM(p, s) do { void* _t; cudaGetSymbolAddress(&_t, s); p = (decltype(p))_t; } while (0)

static GArgs ga(const bf16* Ah, const bf16* Al, long lda,
                const bf16* Bh, const bf16* Bl, long ldb,
                float* C, long ldc, int Kdim, const float* bias)
{
    GArgs g = {};
    g.Ah = Ah; g.Al = Al; g.lda = lda;
    g.Bh = Bh; g.Bl = Bl; g.ldb = ldb;
    g.C = C; g.ldc = ldc; g.Kdim = Kdim; g.bias = bias;
    return g;
}

extern "C" void kernel_launch(void* const* d_in, const int* in_sizes, int n_in,
                              void* d_out, int out_size)
{
    const float* x      = (const float*)d_in[0];
    const float* attn_w = (const float*)d_in[1];
    const float* gate_W = (const float*)d_in[2];
    const float* gate_b = (const float*)d_in[3];
    const float* eW1 = (const float*)d_in[4];
    const float* eb1 = (const float*)d_in[5];
    const float* eW2 = (const float*)d_in[6];
    const float* eb2 = (const float*)d_in[7];
    const float* Wq = (const float*)d_in[8];
    const float* bq = (const float*)d_in[9];
    const float* Wk = (const float*)d_in[10];
    const float* bk = (const float*)d_in[11];
    const float* Wv = (const float*)d_in[12];
    const float* bv = (const float*)d_in[13];
    const float* Wo = (const float*)d_in[14];
    const float* bo = (const float*)d_in[15];
    const float* fW1 = (const float*)d_in[16];
    const float* fb1 = (const float*)d_in[17];
    const float* fW2 = (const float*)d_in[18];
    const float* fb2 = (const float*)d_in[19];
    float* out = (float*)d_out;

    float *p_scores, *p_bqkv;
    int *p_slot_tok, *p_tile_e;
    bf16 *p_xaggh, *p_xaggl, *p_enth, *p_entl, *p_hbufh, *p_hbufl;
    bf16 *p_qkvh, *p_qkvl, *p_atth, *p_attl, *p_ctxh, *p_ctxl, *p_relh, *p_rell;
    bf16 *p_vth, *p_vtl;
    bf16 *p_eW1h, *p_eW1l, *p_eW2h, *p_eW2l, *p_Wqkvh, *p_Wqkvl;
    bf16 *p_Woh, *p_Wol, *p_fW1h, *p_fW1l, *p_fW2h, *p_fW2l;
    SYM(p_scores, g_scores); SYM(p_bqkv, g_bqkv);
    SYM(p_slot_tok, g_slot_tok); SYM(p_tile_e, g_tile_e);
    SYM(p_xaggh, g_xaggh); SYM(p_xaggl, g_xaggl);
    SYM(p_enth, g_enth); SYM(p_entl, g_entl);
    SYM(p_hbufh, g_hbufh); SYM(p_hbufl, g_hbufl);
    SYM(p_qkvh, g_qkvh); SYM(p_qkvl, g_qkvl);
    SYM(p_atth, g_atth); SYM(p_attl, g_attl);
    SYM(p_ctxh, g_ctxh); SYM(p_ctxl, g_ctxl);
    SYM(p_relh, g_relh); SYM(p_rell, g_rell);
    SYM(p_vth, g_vth); SYM(p_vtl, g_vtl);
    SYM(p_eW1h, g_eW1h); SYM(p_eW1l, g_eW1l); SYM(p_eW2h, g_eW2h); SYM(p_eW2l, g_eW2l);
    SYM(p_Wqkvh, g_Wqkvh); SYM(p_Wqkvl, g_Wqkvl);
    SYM(p_Woh, g_Woh); SYM(p_Wol, g_Wol);
    SYM(p_fW1h, g_fW1h); SYM(p_fW1l, g_fW1l); SYM(p_fW2h, g_fW2h); SYM(p_fW2l, g_fW2l);
    float* p_moebuf = p_scores;   // MoE slot buffer reuses scores (disjoint in time)

    cudaFuncSetAttribute(tc_gemm, cudaFuncAttributeMaxDynamicSharedMemorySize, TC_SMEM);
    dim3 tb(32, 8);

    pool_kernel<<<T_, 256>>>(x, attn_w);
    gate_kernel<<<T_, 256>>>(gate_W, gate_b);
    scan_kernel<<<1, 256>>>();
    place_kernel<<<(T_ + 255) / 256, 256>>>();
    wsplit<<<dim3(H_ / 32, D_ / 32, E_), tb>>>(eW1, p_eW1h, p_eW1l, D_, H_);
    // MoE GEMM 1: A = xagg split (gathered rows), out = hbuf split + relu
    {
        GArgs g = ga(p_xaggh, p_xaggl, D_, p_eW1h, p_eW1l, D_, (float*)0, H_, D_, eb1);
        g.biasExp = (long)H_; g.relu = 1; g.arowIdx = p_slot_tok; g.tileE = p_tile_e;
        g.bExp = (long)D_ * H_;
        g.Ch = p_hbufh; g.Cl = p_hbufl;
        tc_gemm<<<dim3(H_ / TN, MAXTILES), 256, TC_SMEM>>>(g);
    }
    wsplit<<<dim3(O_ / 32, H_ / 32, E_), tb>>>(eW2, p_eW2h, p_eW2l, H_, O_);
    // MoE GEMM 2: A = hbuf split, out = slot-major fp32 buffer
    {
        GArgs g = ga(p_hbufh, p_hbufl, H_, p_eW2h, p_eW2l, H_, p_moebuf, O_, H_, eb2);
        g.biasExp = (long)O_; g.tileE = p_tile_e; g.bExp = (long)H_ * O_;
        tc_gemm<<<dim3(O_ / TN, MAXTILES), 256, TC_SMEM>>>(g);
    }
    combine_kernel<<<T_, 256>>>(p_moebuf);
    // fused QKV: B = concat(Wq,Wk,Wv) transposed+split, C = qkv split
    wsplit<<<dim3(O_ / 32, O_ / 32, 1), tb>>>(Wq, p_Wqkvh, p_Wqkvl, O_, O_);
    wsplit<<<dim3(O_ / 32, O_ / 32, 1), tb>>>(Wk, p_Wqkvh + (size_t)O_ * O_, p_Wqkvl + (size_t)O_ * O_, O_, O_);
    wsplit<<<dim3(O_ / 32, O_ / 32, 1), tb>>>(Wv, p_Wqkvh + (size_t)2 * O_ * O_, p_Wqkvl + (size_t)2 * O_ * O_, O_, O_);
    bcat<<<(O_ + 255) / 256, 256>>>(bq, bk, bv);
    {
        GArgs g = ga(p_enth, p_entl, O_, p_Wqkvh, p_Wqkvl, O_, (float*)0, QKV_, O_, p_bqkv);
        g.Ch = p_qkvh; g.Cl = p_qkvl;
        tc_gemm<<<dim3(QKV_ / TN, T_ / TM), 256, TC_SMEM>>>(g);
    }
    vtsplit<<<dim3(NE_ / 32, HD_ / 32, B_ * NH_), tb>>>();
    // scores = q @ k^T (A = qkv q-section, B = qkv k-section rows)
    {
        GArgs g = ga(p_qkvh, p_qkvl, QKV_, p_qkvh + O_, p_qkvl + O_, QKV_, p_scores, NE_, HD_, 0);
        g.aSB = (long)NE_ * QKV_; g.aSH = HD_;
        g.bSB = (long)NE_ * QKV_; g.bSH = HD_;
        g.cSB = (long)NH_ * NE_ * NE_; g.cSH = (long)NE_ * NE_;
        tc_gemm<<<dim3(NE_ / TN, NE_ / TM, B_ * NH_), 256, TC_SMEM>>>(g);
    }
    attn_softmax_kernel<<<B_ * NH_ * NE_, 256>>>();
    // ctx = attn @ v (A = att split, B = Vt split), out = ctx split
    {
        GArgs g = ga(p_atth, p_attl, NE_, p_vth, p_vtl, NE_, (float*)0, O_, NE_, 0);
        g.aSB = (long)NH_ * NE_ * NE_; g.aSH = (long)NE_ * NE_;
        g.bSB = (long)NH_ * HD_ * NE_; g.bSH = (long)HD_ * NE_;
        g.cSB = (long)NE_ * O_; g.cSH = HD_;
        g.Ch = p_ctxh; g.Cl = p_ctxl;
        tc_gemm<<<dim3(1, NE_ / TM, B_ * NH_), 256, TC_SMEM>>>(g);
    }
    // Wo: A = ctx split, out = rel split
    wsplit<<<dim3(O_ / 32, O_ / 32, 1), tb>>>(Wo, p_Woh, p_Wol, O_, O_);
    {
        GArgs g = ga(p_ctxh, p_ctxl, O_, p_Woh, p_Wol, O_, (float*)0, O_, O_, bo);
        g.Ch = p_relh; g.Cl = p_rell;
        tc_gemm<<<dim3(O_ / TN, T_ / TM), 256, TC_SMEM>>>(g);
    }
    // FFN1: A = rel split, relu, out = hbuf split
    wsplit<<<dim3(FH_ / 32, O_ / 32, 1), tb>>>(fW1, p_fW1h, p_fW1l, O_, FH_);
    {
        GArgs g = ga(p_relh, p_rell, O_, p_fW1h, p_fW1l, O_, (float*)0, FH_, O_, fb1);
        g.relu = 1;
        g.Ch = p_hbufh; g.Cl = p_hbufl;
        tc_gemm<<<dim3(FH_ / TN, T_ / TM), 256, TC_SMEM>>>(g);
    }
    // FFN2: A = hbuf split, out = final fp32
    wsplit<<<dim3(O_ / 32, FH_ / 32, 1), tb>>>(fW2, p_fW2h, p_fW2l, FH_, O_);
    tc_gemm<<<dim3(O_ / TN, T_ / TM), 256, TC_SMEM>>>(
        ga(p_hbufh, p_hbufl, FH_, p_fW2h, p_fW2l, FH_, out, O_, FH_, fb2));
}

// round 13
// speedup vs baseline: 1.3842x; 1.3262x over previous
#include <cuda_runtime.h>
#include <cuda_fp16.h>
#include <math.h>
#include <stdint.h>

#define B_ 8
#define NE_ 1024
#define NO_ 8
#define D_ 1024
#define E_ 8
#define H_ 2048
#define O_ 1024
#define NH_ 8
#define HD_ 128
#define FH_ 4096
#define T_ 8192
#define QKV_ (3 * O_)
#define TM 128
#define TN 128
#define MAXTILES 136
#define SLOTMAX (MAXTILES * TM)

typedef __half f16;

// ---------- device scratch ----------
__device__ float g_xagg[(size_t)T_ * D_];                    // fp32 for gate
__device__ int   g_topi[T_ * 2];
__device__ float g_gate[T_ * 2];
__device__ int   g_cnt[E_], g_off[E_ + 1], g_fill[E_];
__device__ int   g_tile_e[MAXTILES];
__device__ int   g_slot_tok[SLOTMAX];
__device__ int   g_tok_slot[T_ * 2];
__device__ float g_scores[(size_t)B_ * NH_ * NE_ * NE_];     // fp32 scores; also MoE slot buf
__device__ float g_bqkv[QKV_];
// split fp16 activations (hi/lo pairs where used as A; hi doubles as B operand)
__device__ f16 g_xaggh[(size_t)T_ * D_],  g_xaggl[(size_t)T_ * D_];
__device__ f16 g_enth[(size_t)T_ * O_],   g_entl[(size_t)T_ * O_];
__device__ f16 g_hbufh[(size_t)SLOTMAX * H_], g_hbufl[(size_t)SLOTMAX * H_]; // also ffn hidden
__device__ f16 g_qkvh[(size_t)T_ * QKV_], g_qkvl[(size_t)T_ * QKV_];
__device__ f16 g_atth[(size_t)B_ * NH_ * NE_ * NE_], g_attl[(size_t)B_ * NH_ * NE_ * NE_];
__device__ f16 g_ctxh[(size_t)T_ * O_],   g_ctxl[(size_t)T_ * O_];
__device__ f16 g_relh[(size_t)T_ * O_],   g_rell[(size_t)T_ * O_];
__device__ f16 g_vt[(size_t)B_ * NH_ * HD_ * NE_];
// fp16 transposed weights Wt[N][K] (single, B-side only)
__device__ f16 g_eW1[(size_t)E_ * D_ * H_];
__device__ f16 g_eW2[(size_t)E_ * H_ * O_];
__device__ f16 g_Wqkv[(size_t)QKV_ * O_];
__device__ f16 g_Wo[(size_t)O_ * O_];
__device__ f16 g_fW1[(size_t)O_ * FH_];
__device__ f16 g_fW2[(size_t)FH_ * O_];

// ---------- helpers ----------
#define SWZ(o) ((o) ^ (((o) >> 3) & 0x70))

__device__ __forceinline__ uint32_t s2u(const void* p) {
    uint32_t a;
    asm("{ .reg .u64 t; cvta.to.shared.u64 t, %1; cvt.u32.u64 %0, t; }" : "=r"(a) : "l"(p));
    return a;
}
__device__ __forceinline__ void split2(float v, f16& h, f16& l) {
    h = __float2half(v);
    l = __float2half(v - __half2float(h));
}
__device__ __forceinline__ void ldsm4(uint32_t* r, uint32_t addr) {
    asm volatile("ldmatrix.sync.aligned.m8n8.x4.shared.b16 {%0,%1,%2,%3}, [%4];"
                 : "=r"(r[0]), "=r"(r[1]), "=r"(r[2]), "=r"(r[3]) : "r"(addr));
}
__device__ __forceinline__ void mma16816(float* c, const uint32_t* a, const uint32_t* b) {
    asm volatile("mma.sync.aligned.m16n8k16.row.col.f32.f16.f16.f32 "
                 "{%0,%1,%2,%3}, {%4,%5,%6,%7}, {%8,%9}, {%0,%1,%2,%3};"
                 : "+f"(c[0]), "+f"(c[1]), "+f"(c[2]), "+f"(c[3])
                 : "r"(a[0]), "r"(a[1]), "r"(a[2]), "r"(a[3]), "r"(b[0]), "r"(b[1]));
}
__device__ __forceinline__ void pack_split(float4 v, uint2& hi, uint2& lo) {
    f16 h0, l0, h1, l1, h2, l2, h3, l3;
    split2(v.x, h0, l0); split2(v.y, h1, l1);
    split2(v.z, h2, l2); split2(v.w, h3, l3);
    __half2 hA = __halves2half2(h0, h1), hB = __halves2half2(h2, h3);
    __half2 lA = __halves2half2(l0, l1), lB = __halves2half2(l2, l3);
    hi = make_uint2(*(uint32_t*)&hA, *(uint32_t*)&hB);
    lo = make_uint2(*(uint32_t*)&lA, *(uint32_t*)&lB);
}

struct GArgs {
    const f16 *Ah, *Al; long lda, aSB, aSH;
    const f16 *Bs; long ldb, bSB, bSH, bExp;     // B[N][K] K-major single fp16
    float* C; long ldc, cSB, cSH;
    f16 *Ch, *Cl;                                 // optional split fp16 output
    const float* bias; long biasExp;
    const int* arowIdx; const int* tileE;
    int Kdim, relu;
};

#define STAGE_ 49152
#define TC_SMEM (2048 + 2 * STAGE_)   // 100352

// ---------- fp16-split tensor-core GEMM (mma.sync), 2-pass: Ah*B + Al*B ----------
// CTA 128x128, KC=64, 8 warps (2x4), double-buffered, pure-copy producers.
__global__ void __launch_bounds__(256, 1) tc_gemm(GArgs g)
{
    int e = 0;
    if (g.tileE) { e = g.tileE[blockIdx.y]; if (e < 0) return; }
    extern __shared__ char smem[];
    char* tiles = (char*)((((uintptr_t)smem) + 1024 + 1023) & ~(uintptr_t)1023);
    const int tid = threadIdx.x, wid = tid >> 5, lid = tid & 31;
    int* srow = (int*)smem;
    const long m0 = (long)blockIdx.y * TM, n0 = (long)blockIdx.x * TN;
    const int z = blockIdx.z, zb = z >> 3, zh = z & 7;

    if (g.arowIdx && tid < TM) srow[tid] = g.arowIdx[m0 + tid];
    __syncthreads();

    const f16* Ahb = g.Ah + (size_t)zb * g.aSB + (size_t)zh * g.aSH;
    const f16* Alb = g.Al + (size_t)zb * g.aSB + (size_t)zh * g.aSH;
    const f16* Bsb = g.Bs + (size_t)zb * g.bSB + (size_t)zh * g.bSH + (size_t)e * g.bExp;

    // A: hi/lo, row = f>>3 (128 rows), c16 = f&7 (8 uint4 = 64 k)
    const uint4 *ahp[4], *alp[4]; bool aval[4];
#pragma unroll
    for (int i = 0; i < 4; i++) {
        int f = tid + 256 * i, arow = f >> 3, c16 = f & 7;
        long r;
        if (g.arowIdx) { int tk = srow[arow]; aval[i] = (tk >= 0); r = (tk >= 0) ? tk : 0; }
        else { aval[i] = true; r = m0 + arow; }
        size_t off = (size_t)r * g.lda + (size_t)c16 * 8;
        ahp[i] = (const uint4*)(Ahb + off);
        alp[i] = (const uint4*)(Alb + off);
    }
    // B: single fp16
    const uint4* bp[4];
#pragma unroll
    for (int i = 0; i < 4; i++) {
        int f = tid + 256 * i, brow = f >> 3, c16 = f & 7;
        bp[i] = (const uint4*)(Bsb + (size_t)(n0 + brow) * g.ldb + (size_t)c16 * 8);
    }

    uint4 pa[8], pb[4];
    const uint4 z4 = make_uint4(0u, 0u, 0u, 0u);
    auto loadregs = [&](int kc) {
        size_t o = (size_t)8 * kc;
#pragma unroll
        for (int i = 0; i < 4; i++) {
            pa[i]     = aval[i] ? ahp[i][o] : z4;
            pa[i + 4] = aval[i] ? alp[i][o] : z4;
        }
#pragma unroll
        for (int i = 0; i < 4; i++) pb[i] = bp[i][o];
    };
    auto sts = [&](int s) {
        char* st = tiles + s * STAGE_;
#pragma unroll
        for (int i = 0; i < 4; i++) {
            int f = tid + 256 * i, arow = f >> 3, c16 = f & 7;
            int sw = SWZ(arow * 128 + c16 * 16);
            *(uint4*)(st + sw)         = pa[i];
            *(uint4*)(st + 16384 + sw) = pa[i + 4];
            *(uint4*)(st + 32768 + sw) = pb[i];
        }
    };

    const uint32_t tilesU = s2u(tiles);
    const int wm = wid >> 2, wn = wid & 3;
    const int m_w = wm * 64, n_w = wn * 32;
    const int jj = lid >> 3, rr = lid & 7;

    float acc[4][4][4];
#pragma unroll
    for (int a = 0; a < 4; a++)
#pragma unroll
        for (int b = 0; b < 4; b++)
#pragma unroll
            for (int c = 0; c < 4; c++) acc[a][b][c] = 0.f;

    auto compute = [&](int s) {
        uint32_t base = tilesU + s * STAGE_;
#pragma unroll
        for (int k16 = 0; k16 < 4; k16++) {
            int kk = k16 * 16;
            uint32_t Ah[4][4], Al[4][4];
#pragma unroll
            for (int mf = 0; mf < 4; mf++) {
                int row = m_w + mf * 16 + (jj & 1) * 8 + rr;
                int kb = (kk + (jj >> 1) * 8) * 2;
                uint32_t off = (uint32_t)(row * 128 + (kb ^ ((row & 7) * 16)));
                ldsm4(Ah[mf], base + off);
                ldsm4(Al[mf], base + 16384 + off);
            }
            uint32_t Bs[2][4];
#pragma unroll
            for (int np = 0; np < 2; np++) {
                int row = n_w + np * 16 + (jj >> 1) * 8 + rr;
                int kb = (kk + (jj & 1) * 8) * 2;
                uint32_t off = (uint32_t)(row * 128 + (kb ^ ((row & 7) * 16)));
                ldsm4(Bs[np], base + 32768 + off);
            }
#pragma unroll
            for (int pass = 0; pass < 2; pass++)
#pragma unroll
                for (int mf = 0; mf < 4; mf++)
#pragma unroll
                    for (int nf = 0; nf < 4; nf++) {
                        const uint32_t* a = pass ? Al[mf] : Ah[mf];
                        mma16816(acc[mf][nf], a, &Bs[nf >> 1][(nf & 1) * 2]);
                    }
        }
    };

    const int nC = g.Kdim >> 6;
    loadregs(0);
    sts(0);
    __syncthreads();
    for (int kc = 0; kc < nC; kc++) {
        if (kc + 1 < nC) loadregs(kc + 1);
        compute(kc & 1);
        if (kc + 1 < nC) {
            sts((kc + 1) & 1);
            __syncthreads();
        }
    }

    // ---------- epilogue ----------
    const float* biasp = g.bias ? (g.bias + (size_t)e * g.biasExp + n0) : (const float*)0;
    size_t cbase = (size_t)zb * g.cSB + (size_t)zh * g.cSH;
#pragma unroll
    for (int mf = 0; mf < 4; mf++) {
#pragma unroll
        for (int half = 0; half < 2; half++) {
            int mrow = m_w + mf * 16 + (lid >> 2) + half * 8;
            long gm = m0 + mrow;
            size_t roff = cbase + (size_t)gm * g.ldc + n0;
#pragma unroll
            for (int nf = 0; nf < 4; nf++) {
                int col = n_w + nf * 8 + (lid & 3) * 2;
                float v0 = acc[mf][nf][half * 2 + 0];
                float v1 = acc[mf][nf][half * 2 + 1];
                if (biasp) { v0 += biasp[col]; v1 += biasp[col + 1]; }
                if (g.relu) { v0 = fmaxf(v0, 0.f); v1 = fmaxf(v1, 0.f); }
                if (g.Ch) {
                    f16 h0, l0, h1, l1;
                    split2(v0, h0, l0); split2(v1, h1, l1);
                    *(__half2*)(g.Ch + roff + col) = __halves2half2(h0, h1);
                    *(__half2*)(g.Cl + roff + col) = __halves2half2(l0, l1);
                }
                if (g.C) {
                    g.C[roff + col] = v0;
                    g.C[roff + col + 1] = v1;
                }
            }
        }
    }
}

// ---------- weight transpose: W[K,N](fp32) -> Wt[N,K] fp16 ----------
__global__ void wtrans(const float* __restrict__ W, f16* __restrict__ o, int K, int N)
{
    __shared__ float t[32][33];
    size_t zoff = (size_t)blockIdx.z * K * N;
    W += zoff; o += zoff;
    int n0 = blockIdx.x * 32, k0 = blockIdx.y * 32;
    int tx = threadIdx.x, ty = threadIdx.y;
#pragma unroll
    for (int r = 0; r < 4; r++)
        t[ty + r * 8][tx] = W[(size_t)(k0 + ty + r * 8) * N + n0 + tx];
    __syncthreads();
#pragma unroll
    for (int r = 0; r < 4; r++) {
        int n = n0 + ty + r * 8, k = k0 + tx;
        o[(size_t)n * K + k] = __float2half(t[tx][ty + r * 8]);
    }
}

// ---------- V transpose: qkv v-section (hi) -> Vt[bh][d][m] ----------
__global__ void vtsplit()
{
    __shared__ unsigned short th[32][33];
    int bh = blockIdx.z, b = bh >> 3, h = bh & 7;
    int m0 = blockIdx.x * 32, d0 = blockIdx.y * 32;
    int tx = threadIdx.x, ty = threadIdx.y;
#pragma unroll
    for (int r = 0; r < 4; r++) {
        size_t src = ((size_t)b * NE_ + m0 + ty + r * 8) * QKV_ + 2 * O_ + h * HD_ + d0 + tx;
        th[ty + r * 8][tx] = *(const unsigned short*)&g_qkvh[src];
    }
    __syncthreads();
#pragma unroll
    for (int r = 0; r < 4; r++) {
        int d = d0 + ty + r * 8, m = m0 + tx;
        *(unsigned short*)&g_vt[((size_t)bh * HD_ + d) * NE_ + m] = th[tx][ty + r * 8];
    }
}

// ---------- bias concat for fused QKV ----------
__global__ void bcat(const float* __restrict__ bq, const float* __restrict__ bk,
                     const float* __restrict__ bv)
{
    int i = blockIdx.x * 256 + threadIdx.x;
    if (i < O_) {
        g_bqkv[i] = bq[i];
        g_bqkv[O_ + i] = bk[i];
        g_bqkv[2 * O_ + i] = bv[i];
    }
}

// ---------- 1) pooling (single pass; fp32 + split out; zeroes MoE counters) ----------
__global__ void __launch_bounds__(256) pool_kernel(const float* __restrict__ x,
                                                   const float* __restrict__ attn_w)
{
    const int t = blockIdx.x, tid = threadIdx.x;
    if (t == 0 && tid < E_) { g_cnt[tid] = 0; g_fill[tid] = 0; }
    const float* base = x + (size_t)t * NO_ * D_;
    float4 aw = ((const float4*)attn_w)[tid];
    float4 xv[NO_];
    float p[NO_];
#pragma unroll
    for (int o = 0; o < NO_; o++) {
        xv[o] = ((const float4*)(base + (size_t)o * D_))[tid];
        p[o] = xv[o].x * aw.x + xv[o].y * aw.y + xv[o].z * aw.z + xv[o].w * aw.w;
    }
#pragma unroll
    for (int off = 16; off; off >>= 1)
#pragma unroll
        for (int o = 0; o < NO_; o++) p[o] += __shfl_down_sync(0xffffffffu, p[o], off);
    __shared__ float sm[NO_][8], wsh[NO_];
    const int w = tid >> 5;
    if ((tid & 31) == 0)
#pragma unroll
        for (int o = 0; o < NO_; o++) sm[o][w] = p[o];
    __syncthreads();
    if (tid == 0) {
        float l[NO_];
#pragma unroll
        for (int o = 0; o < NO_; o++) {
            float s = 0.f;
#pragma unroll
            for (int ww = 0; ww < 8; ww++) s += sm[o][ww];
            l[o] = s;
        }
        float mx = l[0];
#pragma unroll
        for (int o = 1; o < NO_; o++) mx = fmaxf(mx, l[o]);
        float ss = 0.f;
#pragma unroll
        for (int o = 0; o < NO_; o++) { float ev = expf(l[o] - mx); wsh[o] = ev; ss += ev; }
        float inv = 1.f / ss;
#pragma unroll
        for (int o = 0; o < NO_; o++) wsh[o] *= inv;
    }
    __syncthreads();
    float4 ov = make_float4(0.f, 0.f, 0.f, 0.f);
#pragma unroll
    for (int o = 0; o < NO_; o++) {
        float wo = wsh[o];
        ov.x = fmaf(wo, xv[o].x, ov.x); ov.y = fmaf(wo, xv[o].y, ov.y);
        ov.z = fmaf(wo, xv[o].z, ov.z); ov.w = fmaf(wo, xv[o].w, ov.w);
    }
    ((float4*)(g_xagg + (size_t)t * D_))[tid] = ov;
    uint2 hi, lo; pack_split(ov, hi, lo);
    ((uint2*)(g_xaggh + (size_t)t * D_))[tid] = hi;
    ((uint2*)(g_xaggl + (size_t)t * D_))[tid] = lo;
}

// ---------- 2a) gating (fp32, unchanged -> routing immune to fp16) ----------
__global__ void __launch_bounds__(256) gate_kernel(const float* __restrict__ gW,
                                                   const float* __restrict__ gb)
{
    const int t = blockIdx.x, tid = threadIdx.x;
    float4 xv = ((const float4*)(g_xagg + (size_t)t * D_))[tid];
    float xs[4] = {xv.x, xv.y, xv.z, xv.w};
    const float* gr = gW + (size_t)tid * 4 * E_;
    float acc[E_];
#pragma unroll
    for (int e = 0; e < E_; e++) acc[e] = 0.f;
#pragma unroll
    for (int r = 0; r < 4; r++) {
        float4 w0 = *(const float4*)(gr + r * E_);
        float4 w1 = *(const float4*)(gr + r * E_ + 4);
        acc[0] = fmaf(xs[r], w0.x, acc[0]); acc[1] = fmaf(xs[r], w0.y, acc[1]);
        acc[2] = fmaf(xs[r], w0.z, acc[2]); acc[3] = fmaf(xs[r], w0.w, acc[3]);
        acc[4] = fmaf(xs[r], w1.x, acc[4]); acc[5] = fmaf(xs[r], w1.y, acc[5]);
        acc[6] = fmaf(xs[r], w1.z, acc[6]); acc[7] = fmaf(xs[r], w1.w, acc[7]);
    }
#pragma unroll
    for (int off = 16; off; off >>= 1)
#pragma unroll
        for (int e = 0; e < E_; e++) acc[e] += __shfl_down_sync(0xffffffffu, acc[e], off);
    __shared__ float sm[E_][8];
    const int w = tid >> 5;
    if ((tid & 31) == 0)
#pragma unroll
        for (int e = 0; e < E_; e++) sm[e][w] = acc[e];
    __syncthreads();
    if (tid == 0) {
        float l[E_];
#pragma unroll
        for (int e = 0; e < E_; e++) {
            float s = gb[e];
#pragma unroll
            for (int ww = 0; ww < 8; ww++) s += sm[e][ww];
            l[e] = s;
        }
        int i0 = 0;
#pragma unroll
        for (int e = 1; e < E_; e++) if (l[e] > l[i0]) i0 = e;
        int i1 = -1;
#pragma unroll
        for (int e = 0; e < E_; e++) if (e != i0 && (i1 < 0 || l[e] > l[i1])) i1 = e;
        float g0 = 1.f / (1.f + expf(l[i1] - l[i0]));
        g_topi[2 * t] = i0; g_topi[2 * t + 1] = i1;
        g_gate[2 * t] = g0; g_gate[2 * t + 1] = 1.f - g0;
        atomicAdd(&g_cnt[i0], 1); atomicAdd(&g_cnt[i1], 1);
    }
}

// ---------- 2b) scan + slot init ----------
__global__ void scan_kernel()
{
    if (threadIdx.x == 0) {
        int off = 0;
        for (int e = 0; e < E_; e++) {
            g_off[e] = off;
            int tiles = (g_cnt[e] + TM - 1) / TM;
            for (int tt = 0; tt < tiles; tt++) g_tile_e[off / TM + tt] = e;
            off += tiles * TM;
        }
        g_off[E_] = off;
        for (int tt = off / TM; tt < MAXTILES; tt++) g_tile_e[tt] = -1;
    }
    for (int s = threadIdx.x; s < SLOTMAX; s += blockDim.x) g_slot_tok[s] = -1;
}

// ---------- 2c) place ----------
__global__ void place_kernel()
{
    int t = blockIdx.x * blockDim.x + threadIdx.x;
    if (t >= T_) return;
#pragma unroll
    for (int j = 0; j < 2; j++) {
        int e = g_topi[2 * t + j];
        int pos = atomicAdd(&g_fill[e], 1);
        int s = g_off[e] + pos;
        g_slot_tok[s] = t;
        g_tok_slot[2 * t + j] = s;
    }
}

// ---------- 2f) combine: ent = g0*buf[s0] + g1*buf[s1], emit split ----------
__global__ void __launch_bounds__(256) combine_kernel(const float* __restrict__ buf)
{
    const int t = blockIdx.x, tid = threadIdx.x;
    int s0 = g_tok_slot[2 * t], s1 = g_tok_slot[2 * t + 1];
    float w0 = g_gate[2 * t], w1 = g_gate[2 * t + 1];
    float4 a = ((const float4*)(buf + (size_t)s0 * O_))[tid];
    float4 b = ((const float4*)(buf + (size_t)s1 * O_))[tid];
    float4 o;
    o.x = w0 * a.x + w1 * b.x; o.y = w0 * a.y + w1 * b.y;
    o.z = w0 * a.z + w1 * b.z; o.w = w0 * a.w + w1 * b.w;
    uint2 hi, lo; pack_split(o, hi, lo);
    ((uint2*)(g_enth + (size_t)t * O_))[tid] = hi;
    ((uint2*)(g_entl + (size_t)t * O_))[tid] = lo;
}

// ---------- 3b) softmax: fp32 scores -> split fp16 attn ----------
__global__ void __launch_bounds__(256) attn_softmax_kernel()
{
    const int tid = threadIdx.x;
    const size_t row = (size_t)blockIdx.x * NE_;
    float4 v = ((const float4*)(g_scores + row))[tid];
    const float sc = 0.08838834764831845f;
    v.x *= sc; v.y *= sc; v.z *= sc; v.w *= sc;
    float m = fmaxf(fmaxf(v.x, v.y), fmaxf(v.z, v.w));
#pragma unroll
    for (int off = 16; off; off >>= 1) m = fmaxf(m, __shfl_xor_sync(0xffffffffu, m, off));
    __shared__ float sr[8];
    const int w = tid >> 5;
    if ((tid & 31) == 0) sr[w] = m;
    __syncthreads();
    float gm = sr[0];
#pragma unroll
    for (int i = 1; i < 8; i++) gm = fmaxf(gm, sr[i]);
    float e0 = expf(v.x - gm), e1 = expf(v.y - gm), e2 = expf(v.z - gm), e3 = expf(v.w - gm);
    float s = e0 + e1 + e2 + e3;
#pragma unroll
    for (int off = 16; off; off >>= 1) s += __shfl_xor_sync(0xffffffffu, s, off);
    __syncthreads();
    if ((tid & 31) == 0) sr[w] = s;
    __syncthreads();
    float gs = 0.f;
#pragma unroll
    for (int i = 0; i < 8; i++) gs += sr[i];
    float inv = 1.f / gs;
    float4 p = make_float4(e0 * inv, e1 * inv, e2 * inv, e3 * inv);
    uint2 hi, lo; pack_split(p, hi, lo);
    ((uint2*)(g_atth + row))[tid] = hi;
    ((uint2*)(g_attl + row))[tid] = lo;
}

// ---------- host ----------
#define SYM(p, s) do { void* _t; cudaGetSymbolAddress(&_t, s); p = (decltype(p))_t; } while (0)

static GArgs ga(const f16* Ah, const f16* Al, long lda,
                const f16* Bs, long ldb,
                float* C, long ldc, int Kdim, const float* bias)
{
    GArgs g = {};
    g.Ah = Ah; g.Al = Al; g.lda = lda;
    g.Bs = Bs; g.ldb = ldb;
    g.C = C; g.ldc = ldc; g.Kdim = Kdim; g.bias = bias;
    return g;
}

extern "C" void kernel_launch(void* const* d_in, const int* in_sizes, int n_in,
                              void* d_out, int out_size)
{
    const float* x      = (const float*)d_in[0];
    const float* attn_w = (const float*)d_in[1];
    const float* gate_W = (const float*)d_in[2];
    const float* gate_b = (const float*)d_in[3];
    const float* eW1 = (const float*)d_in[4];
    const float* eb1 = (const float*)d_in[5];
    const float* eW2 = (const float*)d_in[6];
    const float* eb2 = (const float*)d_in[7];
    const float* Wq = (const float*)d_in[8];
    const float* bq = (const float*)d_in[9];
    const float* Wk = (const float*)d_in[10];
    const float* bk = (const float*)d_in[11];
    const float* Wv = (const float*)d_in[12];
    const float* bv = (const float*)d_in[13];
    const float* Wo = (const float*)d_in[14];
    const float* bo = (const float*)d_in[15];
    const float* fW1 = (const float*)d_in[16];
    const float* fb1 = (const float*)d_in[17];
    const float* fW2 = (const float*)d_in[18];
    const float* fb2 = (const float*)d_in[19];
    float* out = (float*)d_out;

    float *p_scores, *p_bqkv;
    int *p_slot_tok, *p_tile_e;
    f16 *p_xaggh, *p_xaggl, *p_enth, *p_entl, *p_hbufh, *p_hbufl;
    f16 *p_qkvh, *p_qkvl, *p_atth, *p_attl, *p_ctxh, *p_ctxl, *p_relh, *p_rell;
    f16 *p_vt, *p_eW1, *p_eW2, *p_Wqkv, *p_Wo, *p_fW1, *p_fW2;
    SYM(p_scores, g_scores); SYM(p_bqkv, g_bqkv);
    SYM(p_slot_tok, g_slot_tok); SYM(p_tile_e, g_tile_e);
    SYM(p_xaggh, g_xaggh); SYM(p_xaggl, g_xaggl);
    SYM(p_enth, g_enth); SYM(p_entl, g_entl);
    SYM(p_hbufh, g_hbufh); SYM(p_hbufl, g_hbufl);
    SYM(p_qkvh, g_qkvh); SYM(p_qkvl, g_qkvl);
    SYM(p_atth, g_atth); SYM(p_attl, g_attl);
    SYM(p_ctxh, g_ctxh); SYM(p_ctxl, g_ctxl);
    SYM(p_relh, g_relh); SYM(p_rell, g_rell);
    SYM(p_vt, g_vt);
    SYM(p_eW1, g_eW1); SYM(p_eW2, g_eW2); SYM(p_Wqkv, g_Wqkv);
    SYM(p_Wo, g_Wo); SYM(p_fW1, g_fW1); SYM(p_fW2, g_fW2);
    float* p_moebuf = p_scores;   // MoE slot buffer reuses scores (disjoint in time)

    cudaFuncSetAttribute(tc_gemm, cudaFuncAttributeMaxDynamicSharedMemorySize, TC_SMEM);
    dim3 tb(32, 8);

    pool_kernel<<<T_, 256>>>(x, attn_w);
    gate_kernel<<<T_, 256>>>(gate_W, gate_b);
    scan_kernel<<<1, 256>>>();
    place_kernel<<<(T_ + 255) / 256, 256>>>();
    wtrans<<<dim3(H_ / 32, D_ / 32, E_), tb>>>(eW1, p_eW1, D_, H_);
    // MoE GEMM 1: A = xagg split (gathered rows), out = hbuf split + relu
    {
        GArgs g = ga(p_xaggh, p_xaggl, D_, p_eW1, D_, (float*)0, H_, D_, eb1);
        g.biasExp = (long)H_; g.relu = 1; g.arowIdx = p_slot_tok; g.tileE = p_tile_e;
        g.bExp = (long)D_ * H_;
        g.Ch = p_hbufh; g.Cl = p_hbufl;
        tc_gemm<<<dim3(H_ / TN, MAXTILES), 256, TC_SMEM>>>(g);
    }
    wtrans<<<dim3(O_ / 32, H_ / 32, E_), tb>>>(eW2, p_eW2, H_, O_);
    // MoE GEMM 2: A = hbuf split, out = slot-major fp32 buffer
    {
        GArgs g = ga(p_hbufh, p_hbufl, H_, p_eW2, H_, p_moebuf, O_, H_, eb2);
        g.biasExp = (long)O_; g.tileE = p_tile_e; g.bExp = (long)H_ * O_;
        tc_gemm<<<dim3(O_ / TN, MAXTILES), 256, TC_SMEM>>>(g);
    }
    combine_kernel<<<T_, 256>>>(p_moebuf);
    // fused QKV
    wtrans<<<dim3(O_ / 32, O_ / 32, 1), tb>>>(Wq, p_Wqkv, O_, O_);
    wtrans<<<dim3(O_ / 32, O_ / 32, 1), tb>>>(Wk, p_Wqkv + (size_t)O_ * O_, O_, O_);
    wtrans<<<dim3(O_ / 32, O_ / 32, 1), tb>>>(Wv, p_Wqkv + (size_t)2 * O_ * O_, O_, O_);
    bcat<<<(O_ + 255) / 256, 256>>>(bq, bk, bv);
    {
        GArgs g = ga(p_enth, p_entl, O_, p_Wqkv, O_, (float*)0, QKV_, O_, p_bqkv);
        g.Ch = p_qkvh; g.Cl = p_qkvl;
        tc_gemm<<<dim3(QKV_ / TN, T_ / TM), 256, TC_SMEM>>>(g);
    }
    vtsplit<<<dim3(NE_ / 32, HD_ / 32, B_ * NH_), tb>>>();
    // scores = q @ k^T (A = qkv q-section split, B = qkv k-section hi rows)
    {
        GArgs g = ga(p_qkvh, p_qkvl, QKV_, p_qkvh + O_, QKV_, p_scores, NE_, HD_, 0);
        g.aSB = (long)NE_ * QKV_; g.aSH = HD_;
        g.bSB = (long)NE_ * QKV_; g.bSH = HD_;
        g.cSB = (long)NH_ * NE_ * NE_; g.cSH = (long)NE_ * NE_;
        tc_gemm<<<dim3(NE_ / TN, NE_ / TM, B_ * NH_), 256, TC_SMEM>>>(g);
    }
    attn_softmax_kernel<<<B_ * NH_ * NE_, 256>>>();
    // ctx = attn @ v (A = att split, B = Vt), out = ctx split
    {
        GArgs g = ga(p_atth, p_attl, NE_, p_vt, NE_, (float*)0, O_, NE_, 0);
        g.aSB = (long)NH_ * NE_ * NE_; g.aSH = (long)NE_ * NE_;
        g.bSB = (long)NH_ * HD_ * NE_; g.bSH = (long)HD_ * NE_;
        g.cSB = (long)NE_ * O_; g.cSH = HD_;
        g.Ch = p_ctxh; g.Cl = p_ctxl;
        tc_gemm<<<dim3(1, NE_ / TM, B_ * NH_), 256, TC_SMEM>>>(g);
    }
    // Wo: A = ctx split, out = rel split
    wtrans<<<dim3(O_ / 32, O_ / 32, 1), tb>>>(Wo, p_Wo, O_, O_);
    {
        GArgs g = ga(p_ctxh, p_ctxl, O_, p_Wo, O_, (float*)0, O_, O_, bo);
        g.Ch = p_relh; g.Cl = p_rell;
        tc_gemm<<<dim3(O_ / TN, T_ / TM), 256, TC_SMEM>>>(g);
    }
    // FFN1: A = rel split, relu, out = hbuf split
    wtrans<<<dim3(FH_ / 32, O_ / 32, 1), tb>>>(fW1, p_fW1, O_, FH_);
    {
        GArgs g = ga(p_relh, p_rell, O_, p_fW1, O_, (float*)0, FH_, O_, fb1);
        g.relu = 1;
        g.Ch = p_hbufh; g.Cl = p_hbufl;
        tc_gemm<<<dim3(FH_ / TN, T_ / TM), 256, TC_SMEM>>>(g);
    }
    // FFN2: A = hbuf split, out = final fp32
    wtrans<<<dim3(O_ / 32, FH_ / 32, 1), tb>>>(fW2, p_fW2, FH_, O_);
    tc_gemm<<<dim3(O_ / TN, T_ / TM), 256, TC_SMEM>>>(
        ga(p_hbufh, p_hbufl, FH_, p_fW2, FH_, out, O_, FH_, fb2));
}

// round 16
// speedup vs baseline: 1.5577x; 1.1254x over previous
#include <cuda_runtime.h>
#include <cuda_fp16.h>
#include <math.h>
#include <stdint.h>

#define B_ 8
#define NE_ 1024
#define NO_ 8
#define D_ 1024
#define E_ 8
#define H_ 2048
#define O_ 1024
#define NH_ 8
#define HD_ 128
#define FH_ 4096
#define T_ 8192
#define QKV_ (3 * O_)
#define TM 128
#define TN 128
#define MAXTILES 136
#define SLOTMAX (MAXTILES * TM)

typedef __half f16;

// ---------- device scratch ----------
__device__ float g_xagg[(size_t)T_ * D_];                    // fp32 for gate
__device__ int   g_topi[T_ * 2];
__device__ float g_gate[T_ * 2];
__device__ int   g_cnt[E_], g_off[E_ + 1], g_fill[E_];
__device__ int   g_tile_e[MAXTILES];
__device__ int   g_slot_tok[SLOTMAX];
__device__ int   g_tok_slot[T_ * 2];
__device__ float g_scores[(size_t)B_ * NH_ * NE_ * NE_];     // fp32 scores; also MoE slot buf
__device__ float g_bqkv[QKV_];
// split fp16 activations
__device__ f16 g_xaggh[(size_t)T_ * D_],  g_xaggl[(size_t)T_ * D_];
__device__ f16 g_enth[(size_t)T_ * O_],   g_entl[(size_t)T_ * O_];
__device__ f16 g_hbufh[(size_t)SLOTMAX * H_], g_hbufl[(size_t)SLOTMAX * H_]; // also ffn hidden (hi only)
__device__ f16 g_qkvh[(size_t)T_ * QKV_], g_qkvl[(size_t)T_ * QKV_];          // lo valid only for q-section
__device__ f16 g_atth[(size_t)B_ * NH_ * NE_ * NE_];
__device__ f16 g_ctxh[(size_t)T_ * O_],   g_ctxl[(size_t)T_ * O_];
__device__ f16 g_relh[(size_t)T_ * O_];
__device__ f16 g_vt[(size_t)B_ * NH_ * HD_ * NE_];
// fp16 transposed weights Wt[N][K]
__device__ f16 g_eW1[(size_t)E_ * D_ * H_];
__device__ f16 g_eW2[(size_t)E_ * H_ * O_];
__device__ f16 g_Wqkv[(size_t)QKV_ * O_];
__device__ f16 g_Wo[(size_t)O_ * O_];
__device__ f16 g_fW1[(size_t)O_ * FH_];
__device__ f16 g_fW2[(size_t)FH_ * O_];

// ---------- helpers ----------
#define SWZ(o) ((o) ^ (((o) >> 3) & 0x70))

__device__ __forceinline__ uint32_t s2u(const void* p) {
    uint32_t a;
    asm("{ .reg .u64 t; cvta.to.shared.u64 t, %1; cvt.u32.u64 %0, t; }" : "=r"(a) : "l"(p));
    return a;
}
__device__ __forceinline__ void split2(float v, f16& h, f16& l) {
    h = __float2half(v);
    l = __float2half(v - __half2float(h));
}
__device__ __forceinline__ void ldsm4(uint32_t* r, uint32_t addr) {
    asm volatile("ldmatrix.sync.aligned.m8n8.x4.shared.b16 {%0,%1,%2,%3}, [%4];"
                 : "=r"(r[0]), "=r"(r[1]), "=r"(r[2]), "=r"(r[3]) : "r"(addr));
}
__device__ __forceinline__ void mma16816(float* c, const uint32_t* a, const uint32_t* b) {
    asm volatile("mma.sync.aligned.m16n8k16.row.col.f32.f16.f16.f32 "
                 "{%0,%1,%2,%3}, {%4,%5,%6,%7}, {%8,%9}, {%0,%1,%2,%3};"
                 : "+f"(c[0]), "+f"(c[1]), "+f"(c[2]), "+f"(c[3])
                 : "r"(a[0]), "r"(a[1]), "r"(a[2]), "r"(a[3]), "r"(b[0]), "r"(b[1]));
}
__device__ __forceinline__ void pack_split(float4 v, uint2& hi, uint2& lo) {
    f16 h0, l0, h1, l1, h2, l2, h3, l3;
    split2(v.x, h0, l0); split2(v.y, h1, l1);
    split2(v.z, h2, l2); split2(v.w, h3, l3);
    __half2 hA = __halves2half2(h0, h1), hB = __halves2half2(h2, h3);
    __half2 lA = __halves2half2(l0, l1), lB = __halves2half2(l2, l3);
    hi = make_uint2(*(uint32_t*)&hA, *(uint32_t*)&hB);
    lo = make_uint2(*(uint32_t*)&lA, *(uint32_t*)&lB);
}
__device__ __forceinline__ void pack_hi(float4 v, uint2& hi) {
    __half2 a = __floats2half2_rn(v.x, v.y), b = __floats2half2_rn(v.z, v.w);
    hi = make_uint2(*(uint32_t*)&a, *(uint32_t*)&b);
}

struct GArgs {
    const f16 *Ah, *Al; long lda, aSB, aSH;      // Al == 0 -> single-pass A
    const f16 *Bs; long ldb, bSB, bSH, bExp;     // B[N][K] K-major single fp16
    float* C; long ldc, cSB, cSH;
    f16 *Ch, *Cl;                                 // optional split fp16 output
    long loN;                                     // write Cl only for tiles with n0 < loN
    const float* bias; long biasExp;
    const int* arowIdx; const int* tileE;
    int Kdim, relu;
};

#define STAGE_ 49152
#define TC_SMEM (2048 + 2 * STAGE_)   // 100352

// ---------- fp16-split tensor-core GEMM (mma.sync): Ah*B (+ Al*B if Al) ----------
__global__ void __launch_bounds__(256, 1) tc_gemm(GArgs g)
{
    int e = 0;
    if (g.tileE) { e = g.tileE[blockIdx.y]; if (e < 0) return; }
    extern __shared__ char smem[];
    char* tiles = (char*)((((uintptr_t)smem) + 1024 + 1023) & ~(uintptr_t)1023);
    const int tid = threadIdx.x, wid = tid >> 5, lid = tid & 31;
    int* srow = (int*)smem;
    const long m0 = (long)blockIdx.y * TM, n0 = (long)blockIdx.x * TN;
    const int z = blockIdx.z, zb = z >> 3, zh = z & 7;
    const bool hasAl = (g.Al != 0);

    if (g.arowIdx && tid < TM) srow[tid] = g.arowIdx[m0 + tid];
    __syncthreads();

    const f16* Ahb = g.Ah + (size_t)zb * g.aSB + (size_t)zh * g.aSH;
    const f16* Alb = hasAl ? (g.Al + (size_t)zb * g.aSB + (size_t)zh * g.aSH) : Ahb;
    const f16* Bsb = g.Bs + (size_t)zb * g.bSB + (size_t)zh * g.bSH + (size_t)e * g.bExp;

    const uint4 *ahp[4], *alp[4]; bool aval[4];
#pragma unroll
    for (int i = 0; i < 4; i++) {
        int f = tid + 256 * i, arow = f >> 3, c16 = f & 7;
        long r;
        if (g.arowIdx) { int tk = srow[arow]; aval[i] = (tk >= 0); r = (tk >= 0) ? tk : 0; }
        else { aval[i] = true; r = m0 + arow; }
        size_t off = (size_t)r * g.lda + (size_t)c16 * 8;
        ahp[i] = (const uint4*)(Ahb + off);
        alp[i] = (const uint4*)(Alb + off);
    }
    const uint4* bp[4];
#pragma unroll
    for (int i = 0; i < 4; i++) {
        int f = tid + 256 * i, brow = f >> 3, c16 = f & 7;
        bp[i] = (const uint4*)(Bsb + (size_t)(n0 + brow) * g.ldb + (size_t)c16 * 8);
    }

    uint4 pa[8], pb[4];
    const uint4 z4 = make_uint4(0u, 0u, 0u, 0u);
    auto loadregs = [&](int kc) {
        size_t o = (size_t)8 * kc;
#pragma unroll
        for (int i = 0; i < 4; i++) {
            pa[i] = aval[i] ? ahp[i][o] : z4;
            pa[i + 4] = (hasAl && aval[i]) ? alp[i][o] : z4;
        }
#pragma unroll
        for (int i = 0; i < 4; i++) pb[i] = bp[i][o];
    };
    auto sts = [&](int s) {
        char* st = tiles + s * STAGE_;
#pragma unroll
        for (int i = 0; i < 4; i++) {
            int f = tid + 256 * i, arow = f >> 3, c16 = f & 7;
            int sw = SWZ(arow * 128 + c16 * 16);
            *(uint4*)(st + sw) = pa[i];
            if (hasAl) *(uint4*)(st + 16384 + sw) = pa[i + 4];
            *(uint4*)(st + 32768 + sw) = pb[i];
        }
    };

    const uint32_t tilesU = s2u(tiles);
    const int wm = wid >> 2, wn = wid & 3;
    const int m_w = wm * 64, n_w = wn * 32;
    const int jj = lid >> 3, rr = lid & 7;

    float acc[4][4][4];
#pragma unroll
    for (int a = 0; a < 4; a++)
#pragma unroll
        for (int b = 0; b < 4; b++)
#pragma unroll
            for (int c = 0; c < 4; c++) acc[a][b][c] = 0.f;

    auto compute = [&](int s) {
        uint32_t base = tilesU + s * STAGE_;
#pragma unroll
        for (int k16 = 0; k16 < 4; k16++) {
            int kk = k16 * 16;
            uint32_t Ah[4][4], Al[4][4];
#pragma unroll
            for (int mf = 0; mf < 4; mf++) {
                int row = m_w + mf * 16 + (jj & 1) * 8 + rr;
                int kb = (kk + (jj >> 1) * 8) * 2;
                uint32_t off = (uint32_t)(row * 128 + (kb ^ ((row & 7) * 16)));
                ldsm4(Ah[mf], base + off);
                if (hasAl) ldsm4(Al[mf], base + 16384 + off);
            }
            uint32_t Bs[2][4];
#pragma unroll
            for (int np = 0; np < 2; np++) {
                int row = n_w + np * 16 + (jj >> 1) * 8 + rr;
                int kb = (kk + (jj & 1) * 8) * 2;
                uint32_t off = (uint32_t)(row * 128 + (kb ^ ((row & 7) * 16)));
                ldsm4(Bs[np], base + 32768 + off);
            }
#pragma unroll
            for (int mf = 0; mf < 4; mf++)
#pragma unroll
                for (int nf = 0; nf < 4; nf++)
                    mma16816(acc[mf][nf], Ah[mf], &Bs[nf >> 1][(nf & 1) * 2]);
            if (hasAl) {
#pragma unroll
                for (int mf = 0; mf < 4; mf++)
#pragma unroll
                    for (int nf = 0; nf < 4; nf++)
                        mma16816(acc[mf][nf], Al[mf], &Bs[nf >> 1][(nf & 1) * 2]);
            }
        }
    };

    const int nC = g.Kdim >> 6;
    loadregs(0);
    sts(0);
    __syncthreads();
    for (int kc = 0; kc < nC; kc++) {
        if (kc + 1 < nC) loadregs(kc + 1);
        compute(kc & 1);
        if (kc + 1 < nC) {
            sts((kc + 1) & 1);
            __syncthreads();
        }
    }

    // ---------- epilogue ----------
    const float* biasp = g.bias ? (g.bias + (size_t)e * g.biasExp + n0) : (const float*)0;
    size_t cbase = (size_t)zb * g.cSB + (size_t)zh * g.cSH;
    const bool wantLo = g.Cl && (n0 < g.loN);
#pragma unroll
    for (int mf = 0; mf < 4; mf++) {
#pragma unroll
        for (int half = 0; half < 2; half++) {
            int mrow = m_w + mf * 16 + (lid >> 2) + half * 8;
            long gm = m0 + mrow;
            size_t roff = cbase + (size_t)gm * g.ldc + n0;
#pragma unroll
            for (int nf = 0; nf < 4; nf++) {
                int col = n_w + nf * 8 + (lid & 3) * 2;
                float v0 = acc[mf][nf][half * 2 + 0];
                float v1 = acc[mf][nf][half * 2 + 1];
                if (biasp) { v0 += biasp[col]; v1 += biasp[col + 1]; }
                if (g.relu) { v0 = fmaxf(v0, 0.f); v1 = fmaxf(v1, 0.f); }
                if (g.Ch) {
                    f16 h0, l0, h1, l1;
                    split2(v0, h0, l0); split2(v1, h1, l1);
                    *(__half2*)(g.Ch + roff + col) = __halves2half2(h0, h1);
                    if (wantLo) *(__half2*)(g.Cl + roff + col) = __halves2half2(l0, l1);
                }
                if (g.C) {
                    g.C[roff + col] = v0;
                    g.C[roff + col + 1] = v1;
                }
            }
        }
    }
}

// ---------- weight transpose: W[K,N](fp32) -> Wt[N,K] fp16 ----------
__global__ void wtrans(const float* __restrict__ W, f16* __restrict__ o, int K, int N)
{
    __shared__ float t[32][33];
    size_t zoff = (size_t)blockIdx.z * K * N;
    W += zoff; o += zoff;
    int n0 = blockIdx.x * 32, k0 = blockIdx.y * 32;
    int tx = threadIdx.x, ty = threadIdx.y;
#pragma unroll
    for (int r = 0; r < 4; r++)
        t[ty + r * 8][tx] = W[(size_t)(k0 + ty + r * 8) * N + n0 + tx];
    __syncthreads();
#pragma unroll
    for (int r = 0; r < 4; r++) {
        int n = n0 + ty + r * 8, k = k0 + tx;
        o[(size_t)n * K + k] = __float2half(t[tx][ty + r * 8]);
    }
}

// ---------- V transpose: qkv v-section (hi) -> Vt[bh][d][m] ----------
__global__ void vtsplit()
{
    __shared__ unsigned short th[32][33];
    int bh = blockIdx.z, b = bh >> 3, h = bh & 7;
    int m0 = blockIdx.x * 32, d0 = blockIdx.y * 32;
    int tx = threadIdx.x, ty = threadIdx.y;
#pragma unroll
    for (int r = 0; r < 4; r++) {
        size_t src = ((size_t)b * NE_ + m0 + ty + r * 8) * QKV_ + 2 * O_ + h * HD_ + d0 + tx;
        th[ty + r * 8][tx] = *(const unsigned short*)&g_qkvh[src];
    }
    __syncthreads();
#pragma unroll
    for (int r = 0; r < 4; r++) {
        int d = d0 + ty + r * 8, m = m0 + tx;
        *(unsigned short*)&g_vt[((size_t)bh * HD_ + d) * NE_ + m] = th[tx][ty + r * 8];
    }
}

// ---------- bias concat for fused QKV ----------
__global__ void bcat(const float* __restrict__ bq, const float* __restrict__ bk,
                     const float* __restrict__ bv)
{
    int i = blockIdx.x * 256 + threadIdx.x;
    if (i < O_) {
        g_bqkv[i] = bq[i];
        g_bqkv[O_ + i] = bk[i];
        g_bqkv[2 * O_ + i] = bv[i];
    }
}

// ---------- 1) pooling ----------
__global__ void __launch_bounds__(256) pool_kernel(const float* __restrict__ x,
                                                   const float* __restrict__ attn_w)
{
    const int t = blockIdx.x, tid = threadIdx.x;
    if (t == 0 && tid < E_) { g_cnt[tid] = 0; g_fill[tid] = 0; }
    const float* base = x + (size_t)t * NO_ * D_;
    float4 aw = ((const float4*)attn_w)[tid];
    float4 xv[NO_];
    float p[NO_];
#pragma unroll
    for (int o = 0; o < NO_; o++) {
        xv[o] = ((const float4*)(base + (size_t)o * D_))[tid];
        p[o] = xv[o].x * aw.x + xv[o].y * aw.y + xv[o].z * aw.z + xv[o].w * aw.w;
    }
#pragma unroll
    for (int off = 16; off; off >>= 1)
#pragma unroll
        for (int o = 0; o < NO_; o++) p[o] += __shfl_down_sync(0xffffffffu, p[o], off);
    __shared__ float sm[NO_][8], wsh[NO_];
    const int w = tid >> 5;
    if ((tid & 31) == 0)
#pragma unroll
        for (int o = 0; o < NO_; o++) sm[o][w] = p[o];
    __syncthreads();
    if (tid == 0) {
        float l[NO_];
#pragma unroll
        for (int o = 0; o < NO_; o++) {
            float s = 0.f;
#pragma unroll
            for (int ww = 0; ww < 8; ww++) s += sm[o][ww];
            l[o] = s;
        }
        float mx = l[0];
#pragma unroll
        for (int o = 1; o < NO_; o++) mx = fmaxf(mx, l[o]);
        float ss = 0.f;
#pragma unroll
        for (int o = 0; o < NO_; o++) { float ev = expf(l[o] - mx); wsh[o] = ev; ss += ev; }
        float inv = 1.f / ss;
#pragma unroll
        for (int o = 0; o < NO_; o++) wsh[o] *= inv;
    }
    __syncthreads();
    float4 ov = make_float4(0.f, 0.f, 0.f, 0.f);
#pragma unroll
    for (int o = 0; o < NO_; o++) {
        float wo = wsh[o];
        ov.x = fmaf(wo, xv[o].x, ov.x); ov.y = fmaf(wo, xv[o].y, ov.y);
        ov.z = fmaf(wo, xv[o].z, ov.z); ov.w = fmaf(wo, xv[o].w, ov.w);
    }
    ((float4*)(g_xagg + (size_t)t * D_))[tid] = ov;
    uint2 hi, lo; pack_split(ov, hi, lo);
    ((uint2*)(g_xaggh + (size_t)t * D_))[tid] = hi;
    ((uint2*)(g_xaggl + (size_t)t * D_))[tid] = lo;
}

// ---------- 2a) gating (fp32 -> routing immune) ----------
__global__ void __launch_bounds__(256) gate_kernel(const float* __restrict__ gW,
                                                   const float* __restrict__ gb)
{
    const int t = blockIdx.x, tid = threadIdx.x;
    float4 xv = ((const float4*)(g_xagg + (size_t)t * D_))[tid];
    float xs[4] = {xv.x, xv.y, xv.z, xv.w};
    const float* gr = gW + (size_t)tid * 4 * E_;
    float acc[E_];
#pragma unroll
    for (int e = 0; e < E_; e++) acc[e] = 0.f;
#pragma unroll
    for (int r = 0; r < 4; r++) {
        float4 w0 = *(const float4*)(gr + r * E_);
        float4 w1 = *(const float4*)(gr + r * E_ + 4);
        acc[0] = fmaf(xs[r], w0.x, acc[0]); acc[1] = fmaf(xs[r], w0.y, acc[1]);
        acc[2] = fmaf(xs[r], w0.z, acc[2]); acc[3] = fmaf(xs[r], w0.w, acc[3]);
        acc[4] = fmaf(xs[r], w1.x, acc[4]); acc[5] = fmaf(xs[r], w1.y, acc[5]);
        acc[6] = fmaf(xs[r], w1.z, acc[6]); acc[7] = fmaf(xs[r], w1.w, acc[7]);
    }
#pragma unroll
    for (int off = 16; off; off >>= 1)
#pragma unroll
        for (int e = 0; e < E_; e++) acc[e] += __shfl_down_sync(0xffffffffu, acc[e], off);
    __shared__ float sm[E_][8];
    const int w = tid >> 5;
    if ((tid & 31) == 0)
#pragma unroll
        for (int e = 0; e < E_; e++) sm[e][w] = acc[e];
    __syncthreads();
    if (tid == 0) {
        float l[E_];
#pragma unroll
        for (int e = 0; e < E_; e++) {
            float s = gb[e];
#pragma unroll
            for (int ww = 0; ww < 8; ww++) s += sm[e][ww];
            l[e] = s;
        }
        int i0 = 0;
#pragma unroll
        for (int e = 1; e < E_; e++) if (l[e] > l[i0]) i0 = e;
        int i1 = -1;
#pragma unroll
        for (int e = 0; e < E_; e++) if (e != i0 && (i1 < 0 || l[e] > l[i1])) i1 = e;
        float g0 = 1.f / (1.f + expf(l[i1] - l[i0]));
        g_topi[2 * t] = i0; g_topi[2 * t + 1] = i1;
        g_gate[2 * t] = g0; g_gate[2 * t + 1] = 1.f - g0;
        atomicAdd(&g_cnt[i0], 1); atomicAdd(&g_cnt[i1], 1);
    }
}

// ---------- 2b) scan + slot init ----------
__global__ void scan_kernel()
{
    if (threadIdx.x == 0) {
        int off = 0;
        for (int e = 0; e < E_; e++) {
            g_off[e] = off;
            int tiles = (g_cnt[e] + TM - 1) / TM;
            for (int tt = 0; tt < tiles; tt++) g_tile_e[off / TM + tt] = e;
            off += tiles * TM;
        }
        g_off[E_] = off;
        for (int tt = off / TM; tt < MAXTILES; tt++) g_tile_e[tt] = -1;
    }
    for (int s = threadIdx.x; s < SLOTMAX; s += blockDim.x) g_slot_tok[s] = -1;
}

// ---------- 2c) place ----------
__global__ void place_kernel()
{
    int t = blockIdx.x * blockDim.x + threadIdx.x;
    if (t >= T_) return;
#pragma unroll
    for (int j = 0; j < 2; j++) {
        int e = g_topi[2 * t + j];
        int pos = atomicAdd(&g_fill[e], 1);
        int s = g_off[e] + pos;
        g_slot_tok[s] = t;
        g_tok_slot[2 * t + j] = s;
    }
}

// ---------- 2f) combine ----------
__global__ void __launch_bounds__(256) combine_kernel(const float* __restrict__ buf)
{
    const int t = blockIdx.x, tid = threadIdx.x;
    int s0 = g_tok_slot[2 * t], s1 = g_tok_slot[2 * t + 1];
    float w0 = g_gate[2 * t], w1 = g_gate[2 * t + 1];
    float4 a = ((const float4*)(buf + (size_t)s0 * O_))[tid];
    float4 b = ((const float4*)(buf + (size_t)s1 * O_))[tid];
    float4 o;
    o.x = w0 * a.x + w1 * b.x; o.y = w0 * a.y + w1 * b.y;
    o.z = w0 * a.z + w1 * b.z; o.w = w0 * a.w + w1 * b.w;
    uint2 hi, lo; pack_split(o, hi, lo);
    ((uint2*)(g_enth + (size_t)t * O_))[tid] = hi;
    ((uint2*)(g_entl + (size_t)t * O_))[tid] = lo;
}

// ---------- 3b) softmax: fp32 scores -> fp16 attn (hi only) ----------
__global__ void __launch_bounds__(256) attn_softmax_kernel()
{
    const int tid = threadIdx.x;
    const size_t row = (size_t)blockIdx.x * NE_;
    float4 v = ((const float4*)(g_scores + row))[tid];
    const float sc = 0.08838834764831845f;
    v.x *= sc; v.y *= sc; v.z *= sc; v.w *= sc;
    float m = fmaxf(fmaxf(v.x, v.y), fmaxf(v.z, v.w));
#pragma unroll
    for (int off = 16; off; off >>= 1) m = fmaxf(m, __shfl_xor_sync(0xffffffffu, m, off));
    __shared__ float sr[8];
    const int w = tid >> 5;
    if ((tid & 31) == 0) sr[w] = m;
    __syncthreads();
    float gm = sr[0];
#pragma unroll
    for (int i = 1; i < 8; i++) gm = fmaxf(gm, sr[i]);
    float e0 = expf(v.x - gm), e1 = expf(v.y - gm), e2 = expf(v.z - gm), e3 = expf(v.w - gm);
    float s = e0 + e1 + e2 + e3;
#pragma unroll
    for (int off = 16; off; off >>= 1) s += __shfl_xor_sync(0xffffffffu, s, off);
    __syncthreads();
    if ((tid & 31) == 0) sr[w] = s;
    __syncthreads();
    float gs = 0.f;
#pragma unroll
    for (int i = 0; i < 8; i++) gs += sr[i];
    float inv = 1.f / gs;
    float4 p = make_float4(e0 * inv, e1 * inv, e2 * inv, e3 * inv);
    uint2 hi; pack_hi(p, hi);
    ((uint2*)(g_atth + row))[tid] = hi;
}

// ---------- host ----------
#define SYM(p, s) do { void* _t; cudaGetSymbolAddress(&_t, s); p = (decltype(p))_t; } while (0)

static GArgs ga(const f16* Ah, const f16* Al, long lda,
                const f16* Bs, long ldb,
                float* C, long ldc, int Kdim, const float* bias)
{
    GArgs g = {};
    g.Ah = Ah; g.Al = Al; g.lda = lda;
    g.Bs = Bs; g.ldb = ldb;
    g.C = C; g.ldc = ldc; g.Kdim = Kdim; g.bias = bias;
    g.loN = 1L << 40;
    return g;
}

extern "C" void kernel_launch(void* const* d_in, const int* in_sizes, int n_in,
                              void* d_out, int out_size)
{
    const float* x      = (const float*)d_in[0];
    const float* attn_w = (const float*)d_in[1];
    const float* gate_W = (const float*)d_in[2];
    const float* gate_b = (const float*)d_in[3];
    const float* eW1 = (const float*)d_in[4];
    const float* eb1 = (const float*)d_in[5];
    const float* eW2 = (const float*)d_in[6];
    const float* eb2 = (const float*)d_in[7];
    const float* Wq = (const float*)d_in[8];
    const float* bq = (const float*)d_in[9];
    const float* Wk = (const float*)d_in[10];
    const float* bk = (const float*)d_in[11];
    const float* Wv = (const float*)d_in[12];
    const float* bv = (const float*)d_in[13];
    const float* Wo = (const float*)d_in[14];
    const float* bo = (const float*)d_in[15];
    const float* fW1 = (const float*)d_in[16];
    const float* fb1 = (const float*)d_in[17];
    const float* fW2 = (const float*)d_in[18];
    const float* fb2 = (const float*)d_in[19];
    float* out = (float*)d_out;

    float *p_scores, *p_bqkv;
    int *p_slot_tok, *p_tile_e;
    f16 *p_xaggh, *p_xaggl, *p_enth, *p_entl, *p_hbufh, *p_hbufl;
    f16 *p_qkvh, *p_qkvl, *p_atth, *p_ctxh, *p_ctxl, *p_relh;
    f16 *p_vt, *p_eW1, *p_eW2, *p_Wqkv, *p_Wo, *p_fW1, *p_fW2;
    SYM(p_scores, g_scores); SYM(p_bqkv, g_bqkv);
    SYM(p_slot_tok, g_slot_tok); SYM(p_tile_e, g_tile_e);
    SYM(p_xaggh, g_xaggh); SYM(p_xaggl, g_xaggl);
    SYM(p_enth, g_enth); SYM(p_entl, g_entl);
    SYM(p_hbufh, g_hbufh); SYM(p_hbufl, g_hbufl);
    SYM(p_qkvh, g_qkvh); SYM(p_qkvl, g_qkvl);
    SYM(p_atth, g_atth);
    SYM(p_ctxh, g_ctxh); SYM(p_ctxl, g_ctxl);
    SYM(p_relh, g_relh);
    SYM(p_vt, g_vt);
    SYM(p_eW1, g_eW1); SYM(p_eW2, g_eW2); SYM(p_Wqkv, g_Wqkv);
    SYM(p_Wo, g_Wo); SYM(p_fW1, g_fW1); SYM(p_fW2, g_fW2);
    float* p_moebuf = p_scores;

    cudaFuncSetAttribute(tc_gemm, cudaFuncAttributeMaxDynamicSharedMemorySize, TC_SMEM);
    dim3 tb(32, 8);

    pool_kernel<<<T_, 256>>>(x, attn_w);
    gate_kernel<<<T_, 256>>>(gate_W, gate_b);
    scan_kernel<<<1, 256>>>();
    place_kernel<<<(T_ + 255) / 256, 256>>>();
    wtrans<<<dim3(H_ / 32, D_ / 32, E_), tb>>>(eW1, p_eW1, D_, H_);
    // MoE GEMM 1: A = xagg split 2-pass, out = hbuf split + relu
    {
        GArgs g = ga(p_xaggh, p_xaggl, D_, p_eW1, D_, (float*)0, H_, D_, eb1);
        g.biasExp = (long)H_; g.relu = 1; g.arowIdx = p_slot_tok; g.tileE = p_tile_e;
        g.bExp = (long)D_ * H_;
        g.Ch = p_hbufh; g.Cl = p_hbufl;
        tc_gemm<<<dim3(H_ / TN, MAXTILES), 256, TC_SMEM>>>(g);
    }
    wtrans<<<dim3(O_ / 32, H_ / 32, E_), tb>>>(eW2, p_eW2, H_, O_);
    // MoE GEMM 2: A = hbuf split 2-pass, out = slot-major fp32 buffer
    {
        GArgs g = ga(p_hbufh, p_hbufl, H_, p_eW2, H_, p_moebuf, O_, H_, eb2);
        g.biasExp = (long)O_; g.tileE = p_tile_e; g.bExp = (long)H_ * O_;
        tc_gemm<<<dim3(O_ / TN, MAXTILES), 256, TC_SMEM>>>(g);
    }
    combine_kernel<<<T_, 256>>>(p_moebuf);
    // fused QKV (A = ent split 2-pass; lo output only for q-section)
    wtrans<<<dim3(O_ / 32, O_ / 32, 1), tb>>>(Wq, p_Wqkv, O_, O_);
    wtrans<<<dim3(O_ / 32, O_ / 32, 1), tb>>>(Wk, p_Wqkv + (size_t)O_ * O_, O_, O_);
    wtrans<<<dim3(O_ / 32, O_ / 32, 1), tb>>>(Wv, p_Wqkv + (size_t)2 * O_ * O_, O_, O_);
    bcat<<<(O_ + 255) / 256, 256>>>(bq, bk, bv);
    {
        GArgs g = ga(p_enth, p_entl, O_, p_Wqkv, O_, (float*)0, QKV_, O_, p_bqkv);
        g.Ch = p_qkvh; g.Cl = p_qkvl; g.loN = O_;   // lo only for q-section
        tc_gemm<<<dim3(QKV_ / TN, T_ / TM), 256, TC_SMEM>>>(g);
    }
    vtsplit<<<dim3(NE_ / 32, HD_ / 32, B_ * NH_), tb>>>();
    // scores = q @ k^T (A = q split 2-pass, B = k hi rows)
    {
        GArgs g = ga(p_qkvh, p_qkvl, QKV_, p_qkvh + O_, QKV_, p_scores, NE_, HD_, 0);
        g.aSB = (long)NE_ * QKV_; g.aSH = HD_;
        g.bSB = (long)NE_ * QKV_; g.bSH = HD_;
        g.cSB = (long)NH_ * NE_ * NE_; g.cSH = (long)NE_ * NE_;
        tc_gemm<<<dim3(NE_ / TN, NE_ / TM, B_ * NH_), 256, TC_SMEM>>>(g);
    }
    attn_softmax_kernel<<<B_ * NH_ * NE_, 256>>>();
    // ctx = attn @ v (A = atth SINGLE-pass, B = Vt), out = ctx split
    {
        GArgs g = ga(p_atth, (f16*)0, NE_, p_vt, NE_, (float*)0, O_, NE_, 0);
        g.aSB = (long)NH_ * NE_ * NE_; g.aSH = (long)NE_ * NE_;
        g.bSB = (long)NH_ * HD_ * NE_; g.bSH = (long)HD_ * NE_;
        g.cSB = (long)NE_ * O_; g.cSH = HD_;
        g.Ch = p_ctxh; g.Cl = p_ctxl;
        tc_gemm<<<dim3(1, NE_ / TM, B_ * NH_), 256, TC_SMEM>>>(g);
    }
    // Wo: A = ctx split 2-pass, out = rel hi only
    wtrans<<<dim3(O_ / 32, O_ / 32, 1), tb>>>(Wo, p_Wo, O_, O_);
    {
        GArgs g = ga(p_ctxh, p_ctxl, O_, p_Wo, O_, (float*)0, O_, O_, bo);
        g.Ch = p_relh; g.Cl = (f16*)0;
        tc_gemm<<<dim3(O_ / TN, T_ / TM), 256, TC_SMEM>>>(g);
    }
    // FFN1: A = relh SINGLE-pass, relu, out = hbuf hi only
    wtrans<<<dim3(FH_ / 32, O_ / 32, 1), tb>>>(fW1, p_fW1, O_, FH_);
    {
        GArgs g = ga(p_relh, (f16*)0, O_, p_fW1, O_, (float*)0, FH_, O_, fb1);
        g.relu = 1;
        g.Ch = p_hbufh; g.Cl = (f16*)0;
        tc_gemm<<<dim3(FH_ / TN, T_ / TM), 256, TC_SMEM>>>(g);
    }
    // FFN2: A = hbufh SINGLE-pass, out = final fp32
    wtrans<<<dim3(O_ / 32, FH_ / 32, 1), tb>>>(fW2, p_fW2, FH_, O_);
    tc_gemm<<<dim3(O_ / TN, T_ / TM), 256, TC_SMEM>>>(
        ga(p_hbufh, (f16*)0, FH_, p_fW2, FH_, out, O_, FH_, fb2));
}

// round 17
// speedup vs baseline: 1.8480x; 1.1864x over previous
#include <cuda_runtime.h>
#include <cuda_fp16.h>
#include <math.h>
#include <stdint.h>

#define B_ 8
#define NE_ 1024
#define NO_ 8
#define D_ 1024
#define E_ 8
#define H_ 2048
#define O_ 1024
#define NH_ 8
#define HD_ 128
#define FH_ 4096
#define T_ 8192
#define QKV_ (3 * O_)
#define TM 128
#define TN 128
#define MAXTILES 136
#define SLOTMAX (MAXTILES * TM)

typedef __half f16;

// ---------- device scratch ----------
__device__ float g_xagg[(size_t)T_ * D_];                    // fp32 for gate
__device__ int   g_topi[T_ * 2];
__device__ float g_gate[T_ * 2];
__device__ int   g_cnt[E_], g_off[E_ + 1], g_fill[E_];
__device__ int   g_tile_e[MAXTILES];
__device__ int   g_slot_tok[SLOTMAX];
__device__ int   g_tok_slot[T_ * 2];
__device__ float g_scores[(size_t)B_ * NH_ * NE_ * NE_];     // fp32 scores; also MoE slot buf
__device__ float g_bqkv[QKV_];
// fp16 activations (only xagg keeps a lo part)
__device__ f16 g_xaggh[(size_t)T_ * D_],  g_xaggl[(size_t)T_ * D_];
__device__ f16 g_enth[(size_t)T_ * O_];
__device__ f16 g_hbufh[(size_t)SLOTMAX * H_];                // also ffn hidden
__device__ f16 g_qkvh[(size_t)T_ * QKV_];
__device__ f16 g_atth[(size_t)B_ * NH_ * NE_ * NE_];
__device__ f16 g_ctxh[(size_t)T_ * O_];
__device__ f16 g_relh[(size_t)T_ * O_];
__device__ f16 g_vt[(size_t)B_ * NH_ * HD_ * NE_];
// fp16 transposed weights Wt[N][K]
__device__ f16 g_eW1[(size_t)E_ * D_ * H_];
__device__ f16 g_eW2[(size_t)E_ * H_ * O_];
__device__ f16 g_Wqkv[(size_t)QKV_ * O_];
__device__ f16 g_Wo[(size_t)O_ * O_];
__device__ f16 g_fW1[(size_t)O_ * FH_];
__device__ f16 g_fW2[(size_t)FH_ * O_];

// ---------- helpers ----------
#define SWZ(o) ((o) ^ (((o) >> 3) & 0x70))

__device__ __forceinline__ uint32_t s2u(const void* p) {
    uint32_t a;
    asm("{ .reg .u64 t; cvta.to.shared.u64 t, %1; cvt.u32.u64 %0, t; }" : "=r"(a) : "l"(p));
    return a;
}
__device__ __forceinline__ void split2(float v, f16& h, f16& l) {
    h = __float2half(v);
    l = __float2half(v - __half2float(h));
}
__device__ __forceinline__ void ldsm4(uint32_t* r, uint32_t addr) {
    asm volatile("ldmatrix.sync.aligned.m8n8.x4.shared.b16 {%0,%1,%2,%3}, [%4];"
                 : "=r"(r[0]), "=r"(r[1]), "=r"(r[2]), "=r"(r[3]) : "r"(addr));
}
__device__ __forceinline__ void mma16816(float* c, const uint32_t* a, const uint32_t* b) {
    asm volatile("mma.sync.aligned.m16n8k16.row.col.f32.f16.f16.f32 "
                 "{%0,%1,%2,%3}, {%4,%5,%6,%7}, {%8,%9}, {%0,%1,%2,%3};"
                 : "+f"(c[0]), "+f"(c[1]), "+f"(c[2]), "+f"(c[3])
                 : "r"(a[0]), "r"(a[1]), "r"(a[2]), "r"(a[3]), "r"(b[0]), "r"(b[1]));
}
__device__ __forceinline__ void pack_split(float4 v, uint2& hi, uint2& lo) {
    f16 h0, l0, h1, l1, h2, l2, h3, l3;
    split2(v.x, h0, l0); split2(v.y, h1, l1);
    split2(v.z, h2, l2); split2(v.w, h3, l3);
    __half2 hA = __halves2half2(h0, h1), hB = __halves2half2(h2, h3);
    __half2 lA = __halves2half2(l0, l1), lB = __halves2half2(l2, l3);
    hi = make_uint2(*(uint32_t*)&hA, *(uint32_t*)&hB);
    lo = make_uint2(*(uint32_t*)&lA, *(uint32_t*)&lB);
}
__device__ __forceinline__ void pack_hi(float4 v, uint2& hi) {
    __half2 a = __floats2half2_rn(v.x, v.y), b = __floats2half2_rn(v.z, v.w);
    hi = make_uint2(*(uint32_t*)&a, *(uint32_t*)&b);
}

struct GArgs {
    const f16 *Ah, *Al; long lda, aSB, aSH;      // Al == 0 -> single-pass A
    const f16 *Bs; long ldb, bSB, bSH, bExp;     // B[N][K] K-major single fp16
    float* C; long ldc, cSB, cSH;
    f16 *Ch, *Cl;                                 // optional fp16 output (Cl optional lo)
    long loN;                                     // write Cl only for tiles with n0 < loN
    const float* bias; long biasExp;
    const int* arowIdx; const int* tileE;
    int Kdim, relu;
};

#define STAGE_ 49152
#define TC_SMEM (2048 + 2 * STAGE_)   // 100352

// ---------- fp16-split tensor-core GEMM (mma.sync): Ah*B (+ Al*B if Al) ----------
__global__ void __launch_bounds__(256, 1) tc_gemm(GArgs g)
{
    int e = 0;
    if (g.tileE) { e = g.tileE[blockIdx.y]; if (e < 0) return; }
    extern __shared__ char smem[];
    char* tiles = (char*)((((uintptr_t)smem) + 1024 + 1023) & ~(uintptr_t)1023);
    const int tid = threadIdx.x, wid = tid >> 5, lid = tid & 31;
    int* srow = (int*)smem;
    const long m0 = (long)blockIdx.y * TM, n0 = (long)blockIdx.x * TN;
    const int z = blockIdx.z, zb = z >> 3, zh = z & 7;
    const bool hasAl = (g.Al != 0);

    if (g.arowIdx && tid < TM) srow[tid] = g.arowIdx[m0 + tid];
    __syncthreads();

    const f16* Ahb = g.Ah + (size_t)zb * g.aSB + (size_t)zh * g.aSH;
    const f16* Alb = hasAl ? (g.Al + (size_t)zb * g.aSB + (size_t)zh * g.aSH) : Ahb;
    const f16* Bsb = g.Bs + (size_t)zb * g.bSB + (size_t)zh * g.bSH + (size_t)e * g.bExp;

    const uint4 *ahp[4], *alp[4]; bool aval[4];
#pragma unroll
    for (int i = 0; i < 4; i++) {
        int f = tid + 256 * i, arow = f >> 3, c16 = f & 7;
        long r;
        if (g.arowIdx) { int tk = srow[arow]; aval[i] = (tk >= 0); r = (tk >= 0) ? tk : 0; }
        else { aval[i] = true; r = m0 + arow; }
        size_t off = (size_t)r * g.lda + (size_t)c16 * 8;
        ahp[i] = (const uint4*)(Ahb + off);
        alp[i] = (const uint4*)(Alb + off);
    }
    const uint4* bp[4];
#pragma unroll
    for (int i = 0; i < 4; i++) {
        int f = tid + 256 * i, brow = f >> 3, c16 = f & 7;
        bp[i] = (const uint4*)(Bsb + (size_t)(n0 + brow) * g.ldb + (size_t)c16 * 8);
    }

    uint4 pa[8], pb[4];
    const uint4 z4 = make_uint4(0u, 0u, 0u, 0u);
    auto loadregs = [&](int kc) {
        size_t o = (size_t)8 * kc;
#pragma unroll
        for (int i = 0; i < 4; i++) {
            pa[i] = aval[i] ? ahp[i][o] : z4;
            pa[i + 4] = (hasAl && aval[i]) ? alp[i][o] : z4;
        }
#pragma unroll
        for (int i = 0; i < 4; i++) pb[i] = bp[i][o];
    };
    auto sts = [&](int s) {
        char* st = tiles + s * STAGE_;
#pragma unroll
        for (int i = 0; i < 4; i++) {
            int f = tid + 256 * i, arow = f >> 3, c16 = f & 7;
            int sw = SWZ(arow * 128 + c16 * 16);
            *(uint4*)(st + sw) = pa[i];
            if (hasAl) *(uint4*)(st + 16384 + sw) = pa[i + 4];
            *(uint4*)(st + 32768 + sw) = pb[i];
        }
    };

    const uint32_t tilesU = s2u(tiles);
    const int wm = wid >> 2, wn = wid & 3;
    const int m_w = wm * 64, n_w = wn * 32;
    const int jj = lid >> 3, rr = lid & 7;

    float acc[4][4][4];
#pragma unroll
    for (int a = 0; a < 4; a++)
#pragma unroll
        for (int b = 0; b < 4; b++)
#pragma unroll
            for (int c = 0; c < 4; c++) acc[a][b][c] = 0.f;

    auto compute = [&](int s) {
        uint32_t base = tilesU + s * STAGE_;
#pragma unroll
        for (int k16 = 0; k16 < 4; k16++) {
            int kk = k16 * 16;
            uint32_t Ah[4][4], Al[4][4];
#pragma unroll
            for (int mf = 0; mf < 4; mf++) {
                int row = m_w + mf * 16 + (jj & 1) * 8 + rr;
                int kb = (kk + (jj >> 1) * 8) * 2;
                uint32_t off = (uint32_t)(row * 128 + (kb ^ ((row & 7) * 16)));
                ldsm4(Ah[mf], base + off);
                if (hasAl) ldsm4(Al[mf], base + 16384 + off);
            }
            uint32_t Bs[2][4];
#pragma unroll
            for (int np = 0; np < 2; np++) {
                int row = n_w + np * 16 + (jj >> 1) * 8 + rr;
                int kb = (kk + (jj & 1) * 8) * 2;
                uint32_t off = (uint32_t)(row * 128 + (kb ^ ((row & 7) * 16)));
                ldsm4(Bs[np], base + 32768 + off);
            }
#pragma unroll
            for (int mf = 0; mf < 4; mf++)
#pragma unroll
                for (int nf = 0; nf < 4; nf++)
                    mma16816(acc[mf][nf], Ah[mf], &Bs[nf >> 1][(nf & 1) * 2]);
            if (hasAl) {
#pragma unroll
                for (int mf = 0; mf < 4; mf++)
#pragma unroll
                    for (int nf = 0; nf < 4; nf++)
                        mma16816(acc[mf][nf], Al[mf], &Bs[nf >> 1][(nf & 1) * 2]);
            }
        }
    };

    const int nC = g.Kdim >> 6;
    loadregs(0);
    sts(0);
    __syncthreads();
    for (int kc = 0; kc < nC; kc++) {
        if (kc + 1 < nC) loadregs(kc + 1);
        compute(kc & 1);
        if (kc + 1 < nC) {
            sts((kc + 1) & 1);
            __syncthreads();
        }
    }

    // ---------- epilogue ----------
    const float* biasp = g.bias ? (g.bias + (size_t)e * g.biasExp + n0) : (const float*)0;
    size_t cbase = (size_t)zb * g.cSB + (size_t)zh * g.cSH;
    const bool wantLo = g.Cl && (n0 < g.loN);
#pragma unroll
    for (int mf = 0; mf < 4; mf++) {
#pragma unroll
        for (int half = 0; half < 2; half++) {
            int mrow = m_w + mf * 16 + (lid >> 2) + half * 8;
            long gm = m0 + mrow;
            size_t roff = cbase + (size_t)gm * g.ldc + n0;
#pragma unroll
            for (int nf = 0; nf < 4; nf++) {
                int col = n_w + nf * 8 + (lid & 3) * 2;
                float v0 = acc[mf][nf][half * 2 + 0];
                float v1 = acc[mf][nf][half * 2 + 1];
                if (biasp) { v0 += biasp[col]; v1 += biasp[col + 1]; }
                if (g.relu) { v0 = fmaxf(v0, 0.f); v1 = fmaxf(v1, 0.f); }
                if (g.Ch) {
                    f16 h0, l0, h1, l1;
                    split2(v0, h0, l0); split2(v1, h1, l1);
                    *(__half2*)(g.Ch + roff + col) = __halves2half2(h0, h1);
                    if (wantLo) *(__half2*)(g.Cl + roff + col) = __halves2half2(l0, l1);
                }
                if (g.C) {
                    g.C[roff + col] = v0;
                    g.C[roff + col + 1] = v1;
                }
            }
        }
    }
}

// ---------- weight transpose: W[K,N](fp32) -> Wt[N,K] fp16 ----------
__global__ void wtrans(const float* __restrict__ W, f16* __restrict__ o, int K, int N)
{
    __shared__ float t[32][33];
    size_t zoff = (size_t)blockIdx.z * K * N;
    W += zoff; o += zoff;
    int n0 = blockIdx.x * 32, k0 = blockIdx.y * 32;
    int tx = threadIdx.x, ty = threadIdx.y;
#pragma unroll
    for (int r = 0; r < 4; r++)
        t[ty + r * 8][tx] = W[(size_t)(k0 + ty + r * 8) * N + n0 + tx];
    __syncthreads();
#pragma unroll
    for (int r = 0; r < 4; r++) {
        int n = n0 + ty + r * 8, k = k0 + tx;
        o[(size_t)n * K + k] = __float2half(t[tx][ty + r * 8]);
    }
}

// ---------- V transpose: qkv v-section (hi) -> Vt[bh][d][m] ----------
__global__ void vtsplit()
{
    __shared__ unsigned short th[32][33];
    int bh = blockIdx.z, b = bh >> 3, h = bh & 7;
    int m0 = blockIdx.x * 32, d0 = blockIdx.y * 32;
    int tx = threadIdx.x, ty = threadIdx.y;
#pragma unroll
    for (int r = 0; r < 4; r++) {
        size_t src = ((size_t)b * NE_ + m0 + ty + r * 8) * QKV_ + 2 * O_ + h * HD_ + d0 + tx;
        th[ty + r * 8][tx] = *(const unsigned short*)&g_qkvh[src];
    }
    __syncthreads();
#pragma unroll
    for (int r = 0; r < 4; r++) {
        int d = d0 + ty + r * 8, m = m0 + tx;
        *(unsigned short*)&g_vt[((size_t)bh * HD_ + d) * NE_ + m] = th[tx][ty + r * 8];
    }
}

// ---------- bias concat for fused QKV ----------
__global__ void bcat(const float* __restrict__ bq, const float* __restrict__ bk,
                     const float* __restrict__ bv)
{
    int i = blockIdx.x * 256 + threadIdx.x;
    if (i < O_) {
        g_bqkv[i] = bq[i];
        g_bqkv[O_ + i] = bk[i];
        g_bqkv[2 * O_ + i] = bv[i];
    }
}

// ---------- 1) pooling ----------
__global__ void __launch_bounds__(256) pool_kernel(const float* __restrict__ x,
                                                   const float* __restrict__ attn_w)
{
    const int t = blockIdx.x, tid = threadIdx.x;
    if (t == 0 && tid < E_) { g_cnt[tid] = 0; g_fill[tid] = 0; }
    const float* base = x + (size_t)t * NO_ * D_;
    float4 aw = ((const float4*)attn_w)[tid];
    float4 xv[NO_];
    float p[NO_];
#pragma unroll
    for (int o = 0; o < NO_; o++) {
        xv[o] = ((const float4*)(base + (size_t)o * D_))[tid];
        p[o] = xv[o].x * aw.x + xv[o].y * aw.y + xv[o].z * aw.z + xv[o].w * aw.w;
    }
#pragma unroll
    for (int off = 16; off; off >>= 1)
#pragma unroll
        for (int o = 0; o < NO_; o++) p[o] += __shfl_down_sync(0xffffffffu, p[o], off);
    __shared__ float sm[NO_][8], wsh[NO_];
    const int w = tid >> 5;
    if ((tid & 31) == 0)
#pragma unroll
        for (int o = 0; o < NO_; o++) sm[o][w] = p[o];
    __syncthreads();
    if (tid == 0) {
        float l[NO_];
#pragma unroll
        for (int o = 0; o < NO_; o++) {
            float s = 0.f;
#pragma unroll
            for (int ww = 0; ww < 8; ww++) s += sm[o][ww];
            l[o] = s;
        }
        float mx = l[0];
#pragma unroll
        for (int o = 1; o < NO_; o++) mx = fmaxf(mx, l[o]);
        float ss = 0.f;
#pragma unroll
        for (int o = 0; o < NO_; o++) { float ev = expf(l[o] - mx); wsh[o] = ev; ss += ev; }
        float inv = 1.f / ss;
#pragma unroll
        for (int o = 0; o < NO_; o++) wsh[o] *= inv;
    }
    __syncthreads();
    float4 ov = make_float4(0.f, 0.f, 0.f, 0.f);
#pragma unroll
    for (int o = 0; o < NO_; o++) {
        float wo = wsh[o];
        ov.x = fmaf(wo, xv[o].x, ov.x); ov.y = fmaf(wo, xv[o].y, ov.y);
        ov.z = fmaf(wo, xv[o].z, ov.z); ov.w = fmaf(wo, xv[o].w, ov.w);
    }
    ((float4*)(g_xagg + (size_t)t * D_))[tid] = ov;
    uint2 hi, lo; pack_split(ov, hi, lo);
    ((uint2*)(g_xaggh + (size_t)t * D_))[tid] = hi;
    ((uint2*)(g_xaggl + (size_t)t * D_))[tid] = lo;
}

// ---------- 2a) gating (fp32 -> routing immune) ----------
__global__ void __launch_bounds__(256) gate_kernel(const float* __restrict__ gW,
                                                   const float* __restrict__ gb)
{
    const int t = blockIdx.x, tid = threadIdx.x;
    float4 xv = ((const float4*)(g_xagg + (size_t)t * D_))[tid];
    float xs[4] = {xv.x, xv.y, xv.z, xv.w};
    const float* gr = gW + (size_t)tid * 4 * E_;
    float acc[E_];
#pragma unroll
    for (int e = 0; e < E_; e++) acc[e] = 0.f;
#pragma unroll
    for (int r = 0; r < 4; r++) {
        float4 w0 = *(const float4*)(gr + r * E_);
        float4 w1 = *(const float4*)(gr + r * E_ + 4);
        acc[0] = fmaf(xs[r], w0.x, acc[0]); acc[1] = fmaf(xs[r], w0.y, acc[1]);
        acc[2] = fmaf(xs[r], w0.z, acc[2]); acc[3] = fmaf(xs[r], w0.w, acc[3]);
        acc[4] = fmaf(xs[r], w1.x, acc[4]); acc[5] = fmaf(xs[r], w1.y, acc[5]);
        acc[6] = fmaf(xs[r], w1.z, acc[6]); acc[7] = fmaf(xs[r], w1.w, acc[7]);
    }
#pragma unroll
    for (int off = 16; off; off >>= 1)
#pragma unroll
        for (int e = 0; e < E_; e++) acc[e] += __shfl_down_sync(0xffffffffu, acc[e], off);
    __shared__ float sm[E_][8];
    const int w = tid >> 5;
    if ((tid & 31) == 0)
#pragma unroll
        for (int e = 0; e < E_; e++) sm[e][w] = acc[e];
    __syncthreads();
    if (tid == 0) {
        float l[E_];
#pragma unroll
        for (int e = 0; e < E_; e++) {
            float s = gb[e];
#pragma unroll
            for (int ww = 0; ww < 8; ww++) s += sm[e][ww];
            l[e] = s;
        }
        int i0 = 0;
#pragma unroll
        for (int e = 1; e < E_; e++) if (l[e] > l[i0]) i0 = e;
        int i1 = -1;
#pragma unroll
        for (int e = 0; e < E_; e++) if (e != i0 && (i1 < 0 || l[e] > l[i1])) i1 = e;
        float g0 = 1.f / (1.f + expf(l[i1] - l[i0]));
        g_topi[2 * t] = i0; g_topi[2 * t + 1] = i1;
        g_gate[2 * t] = g0; g_gate[2 * t + 1] = 1.f - g0;
        atomicAdd(&g_cnt[i0], 1); atomicAdd(&g_cnt[i1], 1);
    }
}

// ---------- 2b) scan + slot init ----------
__global__ void scan_kernel()
{
    if (threadIdx.x == 0) {
        int off = 0;
        for (int e = 0; e < E_; e++) {
            g_off[e] = off;
            int tiles = (g_cnt[e] + TM - 1) / TM;
            for (int tt = 0; tt < tiles; tt++) g_tile_e[off / TM + tt] = e;
            off += tiles * TM;
        }
        g_off[E_] = off;
        for (int tt = off / TM; tt < MAXTILES; tt++) g_tile_e[tt] = -1;
    }
    for (int s = threadIdx.x; s < SLOTMAX; s += blockDim.x) g_slot_tok[s] = -1;
}

// ---------- 2c) place ----------
__global__ void place_kernel()
{
    int t = blockIdx.x * blockDim.x + threadIdx.x;
    if (t >= T_) return;
#pragma unroll
    for (int j = 0; j < 2; j++) {
        int e = g_topi[2 * t + j];
        int pos = atomicAdd(&g_fill[e], 1);
        int s = g_off[e] + pos;
        g_slot_tok[s] = t;
        g_tok_slot[2 * t + j] = s;
    }
}

// ---------- 2f) combine: ent = g0*buf[s0] + g1*buf[s1] (hi only) ----------
__global__ void __launch_bounds__(256) combine_kernel(const float* __restrict__ buf)
{
    const int t = blockIdx.x, tid = threadIdx.x;
    int s0 = g_tok_slot[2 * t], s1 = g_tok_slot[2 * t + 1];
    float w0 = g_gate[2 * t], w1 = g_gate[2 * t + 1];
    float4 a = ((const float4*)(buf + (size_t)s0 * O_))[tid];
    float4 b = ((const float4*)(buf + (size_t)s1 * O_))[tid];
    float4 o;
    o.x = w0 * a.x + w1 * b.x; o.y = w0 * a.y + w1 * b.y;
    o.z = w0 * a.z + w1 * b.z; o.w = w0 * a.w + w1 * b.w;
    uint2 hi; pack_hi(o, hi);
    ((uint2*)(g_enth + (size_t)t * O_))[tid] = hi;
}

// ---------- 3b) softmax: fp32 scores -> fp16 attn (hi only) ----------
__global__ void __launch_bounds__(256) attn_softmax_kernel()
{
    const int tid = threadIdx.x;
    const size_t row = (size_t)blockIdx.x * NE_;
    float4 v = ((const float4*)(g_scores + row))[tid];
    const float sc = 0.08838834764831845f;
    v.x *= sc; v.y *= sc; v.z *= sc; v.w *= sc;
    float m = fmaxf(fmaxf(v.x, v.y), fmaxf(v.z, v.w));
#pragma unroll
    for (int off = 16; off; off >>= 1) m = fmaxf(m, __shfl_xor_sync(0xffffffffu, m, off));
    __shared__ float sr[8];
    const int w = tid >> 5;
    if ((tid & 31) == 0) sr[w] = m;
    __syncthreads();
    float gm = sr[0];
#pragma unroll
    for (int i = 1; i < 8; i++) gm = fmaxf(gm, sr[i]);
    float e0 = expf(v.x - gm), e1 = expf(v.y - gm), e2 = expf(v.z - gm), e3 = expf(v.w - gm);
    float s = e0 + e1 + e2 + e3;
#pragma unroll
    for (int off = 16; off; off >>= 1) s += __shfl_xor_sync(0xffffffffu, s, off);
    __syncthreads();
    if ((tid & 31) == 0) sr[w] = s;
    __syncthreads();
    float gs = 0.f;
#pragma unroll
    for (int i = 0; i < 8; i++) gs += sr[i];
    float inv = 1.f / gs;
    float4 p = make_float4(e0 * inv, e1 * inv, e2 * inv, e3 * inv);
    uint2 hi; pack_hi(p, hi);
    ((uint2*)(g_atth + row))[tid] = hi;
}

// ---------- host ----------
#define SYM(p, s) do { void* _t; cudaGetSymbolAddress(&_t, s); p = (decltype(p))_t; } while (0)

static GArgs ga(const f16* Ah, const f16* Al, long lda,
                const f16* Bs, long ldb,
                float* C, long ldc, int Kdim, const float* bias)
{
    GArgs g = {};
    g.Ah = Ah; g.Al = Al; g.lda = lda;
    g.Bs = Bs; g.ldb = ldb;
    g.C = C; g.ldc = ldc; g.Kdim = Kdim; g.bias = bias;
    g.loN = 1L << 40;
    return g;
}

extern "C" void kernel_launch(void* const* d_in, const int* in_sizes, int n_in,
                              void* d_out, int out_size)
{
    const float* x      = (const float*)d_in[0];
    const float* attn_w = (const float*)d_in[1];
    const float* gate_W = (const float*)d_in[2];
    const float* gate_b = (const float*)d_in[3];
    const float* eW1 = (const float*)d_in[4];
    const float* eb1 = (const float*)d_in[5];
    const float* eW2 = (const float*)d_in[6];
    const float* eb2 = (const float*)d_in[7];
    const float* Wq = (const float*)d_in[8];
    const float* bq = (const float*)d_in[9];
    const float* Wk = (const float*)d_in[10];
    const float* bk = (const float*)d_in[11];
    const float* Wv = (const float*)d_in[12];
    const float* bv = (const float*)d_in[13];
    const float* Wo = (const float*)d_in[14];
    const float* bo = (const float*)d_in[15];
    const float* fW1 = (const float*)d_in[16];
    const float* fb1 = (const float*)d_in[17];
    const float* fW2 = (const float*)d_in[18];
    const float* fb2 = (const float*)d_in[19];
    float* out = (float*)d_out;

    float *p_scores, *p_bqkv;
    int *p_slot_tok, *p_tile_e;
    f16 *p_xaggh, *p_xaggl, *p_enth, *p_hbufh;
    f16 *p_qkvh, *p_atth, *p_ctxh, *p_relh;
    f16 *p_vt, *p_eW1, *p_eW2, *p_Wqkv, *p_Wo, *p_fW1, *p_fW2;
    SYM(p_scores, g_scores); SYM(p_bqkv, g_bqkv);
    SYM(p_slot_tok, g_slot_tok); SYM(p_tile_e, g_tile_e);
    SYM(p_xaggh, g_xaggh); SYM(p_xaggl, g_xaggl);
    SYM(p_enth, g_enth);
    SYM(p_hbufh, g_hbufh);
    SYM(p_qkvh, g_qkvh);
    SYM(p_atth, g_atth);
    SYM(p_ctxh, g_ctxh);
    SYM(p_relh, g_relh);
    SYM(p_vt, g_vt);
    SYM(p_eW1, g_eW1); SYM(p_eW2, g_eW2); SYM(p_Wqkv, g_Wqkv);
    SYM(p_Wo, g_Wo); SYM(p_fW1, g_fW1); SYM(p_fW2, g_fW2);
    float* p_moebuf = p_scores;

    cudaFuncSetAttribute(tc_gemm, cudaFuncAttributeMaxDynamicSharedMemorySize, TC_SMEM);
    dim3 tb(32, 8);

    pool_kernel<<<T_, 256>>>(x, attn_w);
    gate_kernel<<<T_, 256>>>(gate_W, gate_b);
    scan_kernel<<<1, 256>>>();
    place_kernel<<<(T_ + 255) / 256, 256>>>();
    wtrans<<<dim3(H_ / 32, D_ / 32, E_), tb>>>(eW1, p_eW1, D_, H_);
    // MoE GEMM 1: A = xagg split 2-pass (kept tight), out = hbuf hi + relu
    {
        GArgs g = ga(p_xaggh, p_xaggl, D_, p_eW1, D_, (float*)0, H_, D_, eb1);
        g.biasExp = (long)H_; g.relu = 1; g.arowIdx = p_slot_tok; g.tileE = p_tile_e;
        g.bExp = (long)D_ * H_;
        g.Ch = p_hbufh; g.Cl = (f16*)0;
        tc_gemm<<<dim3(H_ / TN, MAXTILES), 256, TC_SMEM>>>(g);
    }
    wtrans<<<dim3(O_ / 32, H_ / 32, E_), tb>>>(eW2, p_eW2, H_, O_);
    // MoE GEMM 2: A = hbufh SINGLE-pass, out = slot-major fp32 buffer
    {
        GArgs g = ga(p_hbufh, (f16*)0, H_, p_eW2, H_, p_moebuf, O_, H_, eb2);
        g.biasExp = (long)O_; g.tileE = p_tile_e; g.bExp = (long)H_ * O_;
        tc_gemm<<<dim3(O_ / TN, MAXTILES), 256, TC_SMEM>>>(g);
    }
    combine_kernel<<<T_, 256>>>(p_moebuf);
    // fused QKV: A = enth SINGLE-pass, out = qkv hi
    wtrans<<<dim3(O_ / 32, O_ / 32, 1), tb>>>(Wq, p_Wqkv, O_, O_);
    wtrans<<<dim3(O_ / 32, O_ / 32, 1), tb>>>(Wk, p_Wqkv + (size_t)O_ * O_, O_, O_);
    wtrans<<<dim3(O_ / 32, O_ / 32, 1), tb>>>(Wv, p_Wqkv + (size_t)2 * O_ * O_, O_, O_);
    bcat<<<(O_ + 255) / 256, 256>>>(bq, bk, bv);
    {
        GArgs g = ga(p_enth, (f16*)0, O_, p_Wqkv, O_, (float*)0, QKV_, O_, p_bqkv);
        g.Ch = p_qkvh; g.Cl = (f16*)0;
        tc_gemm<<<dim3(QKV_ / TN, T_ / TM), 256, TC_SMEM>>>(g);
    }
    vtsplit<<<dim3(NE_ / 32, HD_ / 32, B_ * NH_), tb>>>();
    // scores = q @ k^T: A = q hi SINGLE-pass, B = k hi rows
    {
        GArgs g = ga(p_qkvh, (f16*)0, QKV_, p_qkvh + O_, QKV_, p_scores, NE_, HD_, 0);
        g.aSB = (long)NE_ * QKV_; g.aSH = HD_;
        g.bSB = (long)NE_ * QKV_; g.bSH = HD_;
        g.cSB = (long)NH_ * NE_ * NE_; g.cSH = (long)NE_ * NE_;
        tc_gemm<<<dim3(NE_ / TN, NE_ / TM, B_ * NH_), 256, TC_SMEM>>>(g);
    }
    attn_softmax_kernel<<<B_ * NH_ * NE_, 256>>>();
    // ctx = attn @ v: A = atth SINGLE-pass, B = Vt, out = ctx hi
    {
        GArgs g = ga(p_atth, (f16*)0, NE_, p_vt, NE_, (float*)0, O_, NE_, 0);
        g.aSB = (long)NH_ * NE_ * NE_; g.aSH = (long)NE_ * NE_;
        g.bSB = (long)NH_ * HD_ * NE_; g.bSH = (long)HD_ * NE_;
        g.cSB = (long)NE_ * O_; g.cSH = HD_;
        g.Ch = p_ctxh; g.Cl = (f16*)0;
        tc_gemm<<<dim3(1, NE_ / TM, B_ * NH_), 256, TC_SMEM>>>(g);
    }
    // Wo: A = ctxh SINGLE-pass, out = rel hi
    wtrans<<<dim3(O_ / 32, O_ / 32, 1), tb>>>(Wo, p_Wo, O_, O_);
    {
        GArgs g = ga(p_ctxh, (f16*)0, O_, p_Wo, O_, (float*)0, O_, O_, bo);
        g.Ch = p_relh; g.Cl = (f16*)0;
        tc_gemm<<<dim3(O_ / TN, T_ / TM), 256, TC_SMEM>>>(g);
    }
    // FFN1: A = relh SINGLE-pass, relu, out = hbuf hi
    wtrans<<<dim3(FH_ / 32, O_ / 32, 1), tb>>>(fW1, p_fW1, O_, FH_);
    {
        GArgs g = ga(p_relh, (f16*)0, O_, p_fW1, O_, (float*)0, FH_, O_, fb1);
        g.relu = 1;
        g.Ch = p_hbufh; g.Cl = (f16*)0;
        tc_gemm<<<dim3(FH_ / TN, T_ / TM), 256, TC_SMEM>>>(g);
    }
    // FFN2: A = hbufh SINGLE-pass, out = final fp32
    wtrans<<<dim3(O_ / 32, FH_ / 32, 1), tb>>>(fW2, p_fW2, FH_, O_);
    tc_gemm<<<dim3(O_ / TN, T_ / TM), 256, TC_SMEM>>>(
        ga(p_hbufh, (f16*)0, FH_, p_fW2, FH_, out, O_, FH_, fb2));
}